// round 1
// baseline (speedup 1.0000x reference)
#include <cuda_runtime.h>
#include <math.h>

#define BB 4
#define SS 2048
#define FF 512
#define HH 8
#define DD 64
#define HD 512
#define MT (BB*SS)   // 8192

// Scratch (static device globals are the sanctioned scratch path)
__device__ float g_Q[BB*HH*SS*DD];
__device__ float g_K[BB*HH*SS*DD];
__device__ float g_V[BB*HH*SS*DD];
__device__ float g_zt[SS];

// ---------------------------------------------------------------------------
// z_hat table: zt[d] = (1 + e^vh / (1 + e^{vh - ah*d})) / sqrt(D)
// ---------------------------------------------------------------------------
__global__ void zhat_kernel(const float* __restrict__ ah, const float* __restrict__ vh)
{
    int i = blockIdx.x * blockDim.x + threadIdx.x;
    if (i < SS) {
        float a = ah[0], v = vh[0];
        float z = 1.0f + expf(v) / (1.0f + expf(v - a * (float)i));
        g_zt[i] = z * 0.125f;   // 1/sqrt(64)
    }
}

// ---------------------------------------------------------------------------
// QKV projection: C[m,n] = sum_k X[m,k]*W[n,k] + bias[n]
// written to [B,H,S,D] layout scratch. sel: 0=Q 1=K 2=V
// 64x64 tile, BK=16, 256 threads, 4x4 microtile
// ---------------------------------------------------------------------------
__global__ __launch_bounds__(256) void qkv_gemm(
    const float* __restrict__ X, const float* __restrict__ W,
    const float* __restrict__ bias, int sel)
{
    __shared__ float As[16][68];
    __shared__ float Bs[16][68];

    float* dst = (sel == 0) ? g_Q : ((sel == 1) ? g_K : g_V);

    int tid = threadIdx.x;
    int tx = tid & 15, ty = tid >> 4;
    int tx4 = tx * 4, ty4 = ty * 4;
    int m0 = blockIdx.y * 64;
    int n0 = blockIdx.x * 64;

    int lr = tid >> 2;          // row within tile 0..63
    int lc = (tid & 3) * 4;     // k offset (float4)

    float acc[4][4];
#pragma unroll
    for (int i = 0; i < 4; i++)
#pragma unroll
        for (int j = 0; j < 4; j++) acc[i][j] = 0.f;

    for (int k0 = 0; k0 < FF; k0 += 16) {
        float4 av = *(const float4*)&X[(size_t)(m0 + lr) * FF + k0 + lc];
        float4 bv = *(const float4*)&W[(size_t)(n0 + lr) * FF + k0 + lc];
        __syncthreads();
        As[lc + 0][lr] = av.x; As[lc + 1][lr] = av.y;
        As[lc + 2][lr] = av.z; As[lc + 3][lr] = av.w;
        Bs[lc + 0][lr] = bv.x; Bs[lc + 1][lr] = bv.y;
        Bs[lc + 2][lr] = bv.z; Bs[lc + 3][lr] = bv.w;
        __syncthreads();
#pragma unroll
        for (int kk = 0; kk < 16; kk++) {
            float4 a = *(const float4*)&As[kk][ty4];
            float4 b = *(const float4*)&Bs[kk][tx4];
            float ar[4] = {a.x, a.y, a.z, a.w};
            float br[4] = {b.x, b.y, b.z, b.w};
#pragma unroll
            for (int i = 0; i < 4; i++)
#pragma unroll
                for (int j = 0; j < 4; j++)
                    acc[i][j] += ar[i] * br[j];
        }
    }

    int hh = n0 >> 6;   // head index (BN=64 == D)
    float bj[4];
#pragma unroll
    for (int j = 0; j < 4; j++) bj[j] = bias[n0 + tx4 + j];

#pragma unroll
    for (int i = 0; i < 4; i++) {
        int m = m0 + ty4 + i;
        int b = m >> 11;      // /2048
        int s = m & 2047;
        float4 o;
        o.x = acc[i][0] + bj[0];
        o.y = acc[i][1] + bj[1];
        o.z = acc[i][2] + bj[2];
        o.w = acc[i][3] + bj[3];
        *(float4*)&dst[(((size_t)(b * HH + hh)) * SS + s) * DD + tx4] = o;
    }
}

// ---------------------------------------------------------------------------
// Flash attention with multiplicative distance bias.
// Block: 64 query rows x full key sweep in 64-key tiles. 256 threads,
// 4x4 microtile for both QK^T and PV. Online softmax, m/l in registers.
// Dynamic smem: QsT[64][65] + KsT[64][65] (reused for P^T) + Vs[64][64] + zt[2048]
// ---------------------------------------------------------------------------
#define QST_OFF 0
#define KST_OFF 4160
#define VS_OFF  8320
#define ZT_OFF  12416
#define ATTN_SMEM_FLOATS (12416 + 2048)
#define ATTN_SMEM_BYTES  (ATTN_SMEM_FLOATS * 4)

__global__ __launch_bounds__(256) void attn_kernel(float* __restrict__ out)
{
    extern __shared__ float sm[];
    float* QsT = sm + QST_OFF;   // [64][65] transposed: QsT[d*65 + row]
    float* KsT = sm + KST_OFF;   // [64][65] transposed: KsT[d*65 + col]; reused as P^T[j*65+row]
    float* Vs  = sm + VS_OFF;    // [64][64] natural:   Vs[j*64 + d]
    float* zts = sm + ZT_OFF;    // [2048]

    int tid = threadIdx.x;
    int tx = tid & 15, ty = tid >> 4;
    int tx4 = tx * 4, ty4 = ty * 4;
    int bh = blockIdx.y;
    int q0 = blockIdx.x * 64;

    const float* Qg = g_Q + (size_t)bh * SS * DD;
    const float* Kg = g_K + (size_t)bh * SS * DD;
    const float* Vg = g_V + (size_t)bh * SS * DD;

    // load z_hat table
    for (int i = tid; i < SS; i += 256) zts[i] = g_zt[i];

    // load Q tile transposed
    for (int idx = tid; idx < 1024; idx += 256) {
        int r = idx >> 4;
        int c4 = (idx & 15) * 4;
        float4 qv = *(const float4*)&Qg[(size_t)(q0 + r) * DD + c4];
        QsT[(c4 + 0) * 65 + r] = qv.x;
        QsT[(c4 + 1) * 65 + r] = qv.y;
        QsT[(c4 + 2) * 65 + r] = qv.z;
        QsT[(c4 + 3) * 65 + r] = qv.w;
    }

    float acc[4][4];
    float mrow[4], lrow[4];
#pragma unroll
    for (int i = 0; i < 4; i++) {
        mrow[i] = -1e30f;
        lrow[i] = 0.f;
#pragma unroll
        for (int j = 0; j < 4; j++) acc[i][j] = 0.f;
    }

    for (int k0 = 0; k0 < SS; k0 += 64) {
        __syncthreads();   // protect KsT(P)/Vs from previous iteration readers
        // load K (transposed) and V (natural)
        for (int idx = tid; idx < 1024; idx += 256) {
            int r = idx >> 4;
            int c4 = (idx & 15) * 4;
            float4 kv = *(const float4*)&Kg[(size_t)(k0 + r) * DD + c4];
            KsT[(c4 + 0) * 65 + r] = kv.x;
            KsT[(c4 + 1) * 65 + r] = kv.y;
            KsT[(c4 + 2) * 65 + r] = kv.z;
            KsT[(c4 + 3) * 65 + r] = kv.w;
            float4 vv = *(const float4*)&Vg[(size_t)(k0 + r) * DD + c4];
            *(float4*)&Vs[r * 64 + c4] = vv;
        }
        __syncthreads();

        // scores: s[i][j] = q_row(ty4+i) . k_col(tx4+j)
        float s[4][4];
#pragma unroll
        for (int i = 0; i < 4; i++)
#pragma unroll
            for (int j = 0; j < 4; j++) s[i][j] = 0.f;

#pragma unroll 8
        for (int kk = 0; kk < 64; kk++) {
            float a0 = QsT[kk * 65 + ty4 + 0];
            float a1 = QsT[kk * 65 + ty4 + 1];
            float a2 = QsT[kk * 65 + ty4 + 2];
            float a3 = QsT[kk * 65 + ty4 + 3];
            float b0 = KsT[kk * 65 + tx4 + 0];
            float b1 = KsT[kk * 65 + tx4 + 1];
            float b2 = KsT[kk * 65 + tx4 + 2];
            float b3 = KsT[kk * 65 + tx4 + 3];
            s[0][0] += a0 * b0; s[0][1] += a0 * b1; s[0][2] += a0 * b2; s[0][3] += a0 * b3;
            s[1][0] += a1 * b0; s[1][1] += a1 * b1; s[1][2] += a1 * b2; s[1][3] += a1 * b3;
            s[2][0] += a2 * b0; s[2][1] += a2 * b1; s[2][2] += a2 * b2; s[2][3] += a2 * b3;
            s[3][0] += a3 * b0; s[3][1] += a3 * b1; s[3][2] += a3 * b2; s[3][3] += a3 * b3;
        }

        // bias + online softmax (row stats reduced across the 16 tx lanes)
#pragma unroll
        for (int i = 0; i < 4; i++) {
            int qi = q0 + ty4 + i;
            float mx = -1e30f;
#pragma unroll
            for (int j = 0; j < 4; j++) {
                int kj = k0 + tx4 + j;
                int dist = abs(qi - kj);
                s[i][j] *= zts[dist];
                mx = fmaxf(mx, s[i][j]);
            }
#pragma unroll
            for (int o = 1; o < 16; o <<= 1)
                mx = fmaxf(mx, __shfl_xor_sync(0xffffffffu, mx, o));
            float mn = fmaxf(mrow[i], mx);
            float sc = expf(mrow[i] - mn);
            float ls = 0.f;
#pragma unroll
            for (int j = 0; j < 4; j++) {
                s[i][j] = expf(s[i][j] - mn);
                ls += s[i][j];
            }
#pragma unroll
            for (int o = 1; o < 16; o <<= 1)
                ls += __shfl_xor_sync(0xffffffffu, ls, o);
            lrow[i] = lrow[i] * sc + ls;
            mrow[i] = mn;
#pragma unroll
            for (int j = 0; j < 4; j++) acc[i][j] *= sc;
        }

        __syncthreads();   // everyone done reading KsT for scores
        // write P^T into KsT buffer: P^T[j][row]
        float* PsT = KsT;
#pragma unroll
        for (int i = 0; i < 4; i++)
#pragma unroll
            for (int j = 0; j < 4; j++)
                PsT[(tx4 + j) * 65 + (ty4 + i)] = s[i][j];
        __syncthreads();

        // PV: acc[i][j] += sum_kk P^T[kk][ty4+i] * Vs[kk][tx4+j]
#pragma unroll 8
        for (int kk = 0; kk < 64; kk++) {
            float a0 = PsT[kk * 65 + ty4 + 0];
            float a1 = PsT[kk * 65 + ty4 + 1];
            float a2 = PsT[kk * 65 + ty4 + 2];
            float a3 = PsT[kk * 65 + ty4 + 3];
            float4 bv = *(const float4*)&Vs[kk * 64 + tx4];
            acc[0][0] += a0 * bv.x; acc[0][1] += a0 * bv.y; acc[0][2] += a0 * bv.z; acc[0][3] += a0 * bv.w;
            acc[1][0] += a1 * bv.x; acc[1][1] += a1 * bv.y; acc[1][2] += a1 * bv.z; acc[1][3] += a1 * bv.w;
            acc[2][0] += a2 * bv.x; acc[2][1] += a2 * bv.y; acc[2][2] += a2 * bv.z; acc[2][3] += a2 * bv.w;
            acc[3][0] += a3 * bv.x; acc[3][1] += a3 * bv.y; acc[3][2] += a3 * bv.z; acc[3][3] += a3 * bv.w;
        }
    }

    // epilogue: out[b, s, h*64 + d]
    int b = bh >> 3;
    int h = bh & 7;
#pragma unroll
    for (int i = 0; i < 4; i++) {
        int qi = q0 + ty4 + i;
        float inv = 1.0f / lrow[i];
        float4 o;
        o.x = acc[i][0] * inv;
        o.y = acc[i][1] * inv;
        o.z = acc[i][2] * inv;
        o.w = acc[i][3] * inv;
        *(float4*)&out[((size_t)(b * SS + qi)) * HD + h * 64 + tx4] = o;
    }
}

// ---------------------------------------------------------------------------
extern "C" void kernel_launch(void* const* d_in, const int* in_sizes, int n_in,
                              void* d_out, int out_size)
{
    const float* x  = (const float*)d_in[0];
    const float* Wq = (const float*)d_in[1];
    const float* bq = (const float*)d_in[2];
    const float* Wk = (const float*)d_in[3];
    const float* bk = (const float*)d_in[4];
    const float* Wv = (const float*)d_in[5];
    const float* bv = (const float*)d_in[6];
    const float* ah = (const float*)d_in[7];
    const float* vh = (const float*)d_in[8];
    float* out = (float*)d_out;

    zhat_kernel<<<SS / 256, 256>>>(ah, vh);

    dim3 gg(HD / 64, MT / 64);
    qkv_gemm<<<gg, 256>>>(x, Wq, bq, 0);
    qkv_gemm<<<gg, 256>>>(x, Wk, bk, 1);
    qkv_gemm<<<gg, 256>>>(x, Wv, bv, 2);

    cudaFuncSetAttribute(attn_kernel,
                         cudaFuncAttributeMaxDynamicSharedMemorySize,
                         ATTN_SMEM_BYTES);
    attn_kernel<<<dim3(SS / 64, BB * HH), 256, ATTN_SMEM_BYTES>>>(out);
}

// round 3
// speedup vs baseline: 2.2483x; 2.2483x over previous
#include <cuda_runtime.h>
#include <cuda_bf16.h>
#include <math.h>
#include <stdint.h>

#define BB 4
#define SS 2048
#define FF 512
#define HH 8
#define DD 64
#define HD 512
#define MT (BB*SS)   // 8192

// ---------------------------------------------------------------------------
// Scratch (static device globals = sanctioned scratch path)
// ---------------------------------------------------------------------------
__device__ __nv_bfloat16 g_Xh[MT*FF];
__device__ __nv_bfloat16 g_Xl[MT*FF];
__device__ __nv_bfloat16 g_Wh[3*HD*FF];
__device__ __nv_bfloat16 g_Wl[3*HD*FF];
__device__ __nv_bfloat16 g_Qh[BB*HH*SS*DD];
__device__ __nv_bfloat16 g_Ql[BB*HH*SS*DD];
__device__ __nv_bfloat16 g_Kh[BB*HH*SS*DD];
__device__ __nv_bfloat16 g_Kl[BB*HH*SS*DD];
__device__ __nv_bfloat16 g_Vh[BB*HH*SS*DD];
__device__ __nv_bfloat16 g_Vl[BB*HH*SS*DD];
__device__ float g_zt[SS];

// ---------------------------------------------------------------------------
// Helpers
// ---------------------------------------------------------------------------
__device__ __forceinline__ uint32_t smem_u32(const void* p) {
    uint32_t a;
    asm("{ .reg .u64 t; cvta.to.shared.u64 t, %1; cvt.u32.u64 %0, t; }"
        : "=r"(a) : "l"(p));
    return a;
}

#define CP_ASYNC16(dst, src) \
    asm volatile("cp.async.cg.shared.global [%0], [%1], 16;" \
        :: "r"(dst), "l"(src) : "memory")
#define CP_COMMIT() asm volatile("cp.async.commit_group;" ::: "memory")
#define CP_WAIT1()  asm volatile("cp.async.wait_group 1;" ::: "memory")

// D += A * B  (m16n8k16, bf16 inputs, fp32 accumulate)
__device__ __forceinline__ void mma_bf16(float* d, const uint32_t* a, const uint32_t* b) {
    asm volatile(
        "mma.sync.aligned.m16n8k16.row.col.f32.bf16.bf16.f32 "
        "{%0,%1,%2,%3}, {%4,%5,%6,%7}, {%8,%9}, {%0,%1,%2,%3};"
        : "+f"(d[0]), "+f"(d[1]), "+f"(d[2]), "+f"(d[3])
        : "r"(a[0]), "r"(a[1]), "r"(a[2]), "r"(a[3]), "r"(b[0]), "r"(b[1]));
}

__device__ __forceinline__ uint32_t pk2(__nv_bfloat16 a, __nv_bfloat16 b) {
    return (uint32_t)__bfloat16_as_ushort(a) | ((uint32_t)__bfloat16_as_ushort(b) << 16);
}

// ---------------------------------------------------------------------------
// z_hat table
// ---------------------------------------------------------------------------
__global__ void zhat_kernel(const float* __restrict__ ah, const float* __restrict__ vh)
{
    int i = blockIdx.x * blockDim.x + threadIdx.x;
    if (i < SS) {
        float a = ah[0], v = vh[0];
        float z = 1.0f + expf(v) / (1.0f + expf(v - a * (float)i));
        g_zt[i] = z * 0.125f;   // includes 1/sqrt(64)
    }
}

// ---------------------------------------------------------------------------
// Split X and W (fp32 -> bf16 hi + bf16 lo)
// ---------------------------------------------------------------------------
#define NX4 (MT*FF/4)          // 1048576 float4
#define NW4 (3*HD*FF/4)        // 196608 float4
#define NW4_1 (HD*FF/4)        // 65536

__global__ __launch_bounds__(256) void split_kernel(
    const float* __restrict__ X, const float* __restrict__ Wq,
    const float* __restrict__ Wk, const float* __restrict__ Wv)
{
    int i = blockIdx.x * 256 + threadIdx.x;
    const float* src;
    __nv_bfloat16 *dh, *dl;
    int off;
    if (i < NX4) {
        src = X; off = i; dh = g_Xh; dl = g_Xl;
    } else {
        int j = i - NX4;
        if (j < NW4_1)            { src = Wq; off = j; }
        else if (j < 2 * NW4_1)   { src = Wk; off = j - NW4_1; }
        else                      { src = Wv; off = j - 2 * NW4_1; }
        dh = g_Wh + (size_t)(j / NW4_1) * HD * FF;
        dl = g_Wl + (size_t)(j / NW4_1) * HD * FF;
    }
    float4 v = ((const float4*)src)[off];
    float vv[4] = {v.x, v.y, v.z, v.w};
    __nv_bfloat16 h[4], l[4];
#pragma unroll
    for (int k = 0; k < 4; k++) {
        h[k] = __float2bfloat16(vv[k]);
        l[k] = __float2bfloat16(vv[k] - __bfloat162float(h[k]));
    }
    size_t o4 = (size_t)off * 4;
    *(__nv_bfloat162*)&dh[o4]     = *(__nv_bfloat162*)&h[0];
    *(__nv_bfloat162*)&dh[o4 + 2] = *(__nv_bfloat162*)&h[2];
    *(__nv_bfloat162*)&dl[o4]     = *(__nv_bfloat162*)&l[0];
    *(__nv_bfloat162*)&dl[o4 + 2] = *(__nv_bfloat162*)&l[2];
}

// ---------------------------------------------------------------------------
// Fused QKV projection via mma.sync, bf16x3 split.
// CTA: 128 m-rows x 128 n-cols. 256 threads = 8 warps stacked along m.
// k staged in 64 chunks, cp.async double-buffered.
// smem row stride 144B (72 bf16) -> conflict-free fragment LDS.
// ---------------------------------------------------------------------------
#define PROW 144
#define PARR 18432        // 128 rows * 144
#define PSTG (4*PARR)     // Xh,Xl,Wh,Wl
#define PROJ_SMEM (2*PSTG)

__global__ __launch_bounds__(256) void proj_mma(
    const float* __restrict__ bq, const float* __restrict__ bk,
    const float* __restrict__ bv, float* __restrict__ out_unused)
{
    extern __shared__ char sm[];
    const int tid = threadIdx.x;
    const int w = tid >> 5, lane = tid & 31;
    const int gr = lane >> 2, qt = lane & 3;
    const int nb = blockIdx.x;          // 0..11
    const int m0 = blockIdx.y * 128;

    float acc[16][4];
#pragma unroll
    for (int i = 0; i < 16; i++)
#pragma unroll
        for (int j = 0; j < 4; j++) acc[i][j] = 0.f;

    auto fill = [&](int stg, int k0) {
        char* dstb = sm + stg * PSTG;
#pragma unroll
        for (int ii = 0; ii < 16; ii++) {
            int idx = ii * 256 + tid;
            int arr = idx >> 10;
            int r = (idx >> 3) & 127;
            int c = idx & 7;
            const __nv_bfloat16* src;
            if (arr == 0)      src = g_Xh + (size_t)(m0 + r) * FF + k0 + c * 8;
            else if (arr == 1) src = g_Xl + (size_t)(m0 + r) * FF + k0 + c * 8;
            else if (arr == 2) src = g_Wh + (size_t)(nb * 128 + r) * FF + k0 + c * 8;
            else               src = g_Wl + (size_t)(nb * 128 + r) * FF + k0 + c * 8;
            uint32_t d = smem_u32(dstb + arr * PARR + r * PROW + c * 16);
            CP_ASYNC16(d, src);
        }
        CP_COMMIT();
    };

    fill(0, 0);
    fill(1, 64);

    const int arow = w * 16 + gr;
#pragma unroll 1
    for (int ks = 0; ks < 8; ks++) {
        CP_WAIT1();
        __syncthreads();
        const char* B  = sm + (ks & 1) * PSTG;
        const char* Xh = B;
        const char* Xl = B + PARR;
        const char* Wh = B + 2 * PARR;
        const char* Wl = B + 3 * PARR;
#pragma unroll
        for (int kf = 0; kf < 4; kf++) {
            int ao = arow * PROW + kf * 32 + qt * 4;
            uint32_t ah[4], al[4];
            ah[0] = *(const uint32_t*)(Xh + ao);
            ah[1] = *(const uint32_t*)(Xh + ao + 8 * PROW);
            ah[2] = *(const uint32_t*)(Xh + ao + 16);
            ah[3] = *(const uint32_t*)(Xh + ao + 8 * PROW + 16);
            al[0] = *(const uint32_t*)(Xl + ao);
            al[1] = *(const uint32_t*)(Xl + ao + 8 * PROW);
            al[2] = *(const uint32_t*)(Xl + ao + 16);
            al[3] = *(const uint32_t*)(Xl + ao + 8 * PROW + 16);
#pragma unroll
            for (int nf = 0; nf < 16; nf++) {
                int bo = (nf * 8 + gr) * PROW + kf * 32 + qt * 4;
                uint32_t bh[2], bl[2];
                bh[0] = *(const uint32_t*)(Wh + bo);
                bh[1] = *(const uint32_t*)(Wh + bo + 16);
                bl[0] = *(const uint32_t*)(Wl + bo);
                bl[1] = *(const uint32_t*)(Wl + bo + 16);
                mma_bf16(acc[nf], ah, bh);
                mma_bf16(acc[nf], ah, bl);
                mma_bf16(acc[nf], al, bh);
            }
        }
        __syncthreads();
        if (ks + 2 < 8) fill(ks & 1, (ks + 2) * 64);
    }

    // epilogue: add bias, split hi/lo, write [b,h,s,d]
    const int r0 = m0 + w * 16 + gr;
#pragma unroll
    for (int nf = 0; nf < 16; nf++) {
        int ng = nb * 128 + nf * 8 + qt * 2;
        int sel = ng >> 9;
        int within = ng & 511;
        const float* bias = (sel == 0) ? bq : (sel == 1) ? bk : bv;
        float b0 = bias[within], b1 = bias[within + 1];
        int h = within >> 6, d = within & 63;
        __nv_bfloat16* dh = (sel == 0) ? g_Qh : (sel == 1) ? g_Kh : g_Vh;
        __nv_bfloat16* dl = (sel == 0) ? g_Ql : (sel == 1) ? g_Kl : g_Vl;
#pragma unroll
        for (int half = 0; half < 2; half++) {
            int m = r0 + half * 8;
            int bb = m >> 11, s = m & 2047;
            float y0 = acc[nf][half * 2 + 0] + b0;
            float y1 = acc[nf][half * 2 + 1] + b1;
            __nv_bfloat16 h0 = __float2bfloat16(y0);
            __nv_bfloat16 h1 = __float2bfloat16(y1);
            __nv_bfloat16 l0 = __float2bfloat16(y0 - __bfloat162float(h0));
            __nv_bfloat16 l1 = __float2bfloat16(y1 - __bfloat162float(h1));
            size_t a = (((size_t)(bb * HH + h)) * SS + s) * DD + d;
            *(uint32_t*)&dh[a] = pk2(h0, h1);
            *(uint32_t*)&dl[a] = pk2(l0, l1);
        }
    }
}

// ---------------------------------------------------------------------------
// Flash attention via mma.sync, bf16x3, register softmax.
// CTA: 128 q-rows (8 warps x m16), key tiles of 64, cp.async double buffer.
// ---------------------------------------------------------------------------
#define AROW 144
#define AARR 9216         // 64 rows * 144
#define ASTG (4*AARR)     // Kh,Kl,Vh,Vl
#define AZT  (2*ASTG)
#define ATTN_SMEM (AZT + SS*4)

__global__ __launch_bounds__(256) void attn_mma(float* __restrict__ out)
{
    extern __shared__ char sm[];
    float* zts = (float*)(sm + AZT);
    const int tid = threadIdx.x;
    const int w = tid >> 5, lane = tid & 31;
    const int gr = lane >> 2, qt = lane & 3;
    const int bh = blockIdx.y;
    const int q0 = blockIdx.x * 128;

    for (int i = tid; i < SS; i += 256) zts[i] = g_zt[i];

    // Q fragments straight from gmem (once)
    const int r0 = q0 + w * 16 + gr;
    const __nv_bfloat16* Qh = g_Qh + (size_t)bh * SS * DD;
    const __nv_bfloat16* Ql = g_Ql + (size_t)bh * SS * DD;
    uint32_t qah[4][4], qal[4][4];
#pragma unroll
    for (int kf = 0; kf < 4; kf++) {
        int col = kf * 16 + qt * 2;
        qah[kf][0] = *(const uint32_t*)(Qh + (size_t)r0 * 64 + col);
        qah[kf][1] = *(const uint32_t*)(Qh + (size_t)(r0 + 8) * 64 + col);
        qah[kf][2] = *(const uint32_t*)(Qh + (size_t)r0 * 64 + col + 8);
        qah[kf][3] = *(const uint32_t*)(Qh + (size_t)(r0 + 8) * 64 + col + 8);
        qal[kf][0] = *(const uint32_t*)(Ql + (size_t)r0 * 64 + col);
        qal[kf][1] = *(const uint32_t*)(Ql + (size_t)(r0 + 8) * 64 + col);
        qal[kf][2] = *(const uint32_t*)(Ql + (size_t)r0 * 64 + col + 8);
        qal[kf][3] = *(const uint32_t*)(Ql + (size_t)(r0 + 8) * 64 + col + 8);
    }

    auto fill = [&](int stg, int k0) {
        char* dstb = sm + stg * ASTG;
#pragma unroll
        for (int ii = 0; ii < 8; ii++) {
            int idx = ii * 256 + tid;
            int arr = idx >> 9;
            int r = (idx >> 3) & 63;
            int c = idx & 7;
            const __nv_bfloat16* src;
            if (arr == 0)      src = g_Kh + ((size_t)bh * SS + k0 + r) * 64 + c * 8;
            else if (arr == 1) src = g_Kl + ((size_t)bh * SS + k0 + r) * 64 + c * 8;
            else if (arr == 2) src = g_Vh + ((size_t)bh * SS + k0 + r) * 64 + c * 8;
            else               src = g_Vl + ((size_t)bh * SS + k0 + r) * 64 + c * 8;
            uint32_t d = smem_u32(dstb + arr * AARR + r * AROW + c * 16);
            CP_ASYNC16(d, src);
        }
        CP_COMMIT();
    };

    fill(0, 0);
    fill(1, 64);

    float O[8][4];
#pragma unroll
    for (int i = 0; i < 8; i++)
#pragma unroll
        for (int j = 0; j < 4; j++) O[i][j] = 0.f;
    float m0r = -1e30f, m1r = -1e30f, l0r = 0.f, l1r = 0.f;

#pragma unroll 1
    for (int kt = 0; kt < 32; kt++) {
        CP_WAIT1();
        __syncthreads();
        const char* B   = sm + (kt & 1) * ASTG;
        const char* cKh = B;
        const char* cKl = B + AARR;
        const char* cVh = B + 2 * AARR;
        const char* cVl = B + 3 * AARR;
        const int k0 = kt * 64;

        // ---- S = Q K^T (bf16x3) ----
        float S[8][4];
#pragma unroll
        for (int i = 0; i < 8; i++)
#pragma unroll
            for (int j = 0; j < 4; j++) S[i][j] = 0.f;

#pragma unroll
        for (int kf = 0; kf < 4; kf++) {
#pragma unroll
            for (int nf = 0; nf < 8; nf++) {
                int bo = (nf * 8 + gr) * AROW + kf * 32 + qt * 4;
                uint32_t bhf[2], blf[2];
                bhf[0] = *(const uint32_t*)(cKh + bo);
                bhf[1] = *(const uint32_t*)(cKh + bo + 16);
                blf[0] = *(const uint32_t*)(cKl + bo);
                blf[1] = *(const uint32_t*)(cKl + bo + 16);
                mma_bf16(S[nf], qah[kf], bhf);
                mma_bf16(S[nf], qah[kf], blf);
                mma_bf16(S[nf], qal[kf], bhf);
            }
        }

        // ---- bias + online softmax (register fragments) ----
        float mt0 = -1e30f, mt1 = -1e30f;
#pragma unroll
        for (int nf = 0; nf < 8; nf++) {
            int c0 = k0 + nf * 8 + qt * 2;
            S[nf][0] *= zts[abs(r0 - c0)];
            S[nf][1] *= zts[abs(r0 - c0 - 1)];
            S[nf][2] *= zts[abs(r0 + 8 - c0)];
            S[nf][3] *= zts[abs(r0 + 8 - c0 - 1)];
            mt0 = fmaxf(mt0, fmaxf(S[nf][0], S[nf][1]));
            mt1 = fmaxf(mt1, fmaxf(S[nf][2], S[nf][3]));
        }
        mt0 = fmaxf(mt0, __shfl_xor_sync(0xffffffffu, mt0, 1));
        mt0 = fmaxf(mt0, __shfl_xor_sync(0xffffffffu, mt0, 2));
        mt1 = fmaxf(mt1, __shfl_xor_sync(0xffffffffu, mt1, 1));
        mt1 = fmaxf(mt1, __shfl_xor_sync(0xffffffffu, mt1, 2));
        float mn0 = fmaxf(m0r, mt0), mn1 = fmaxf(m1r, mt1);
        float a0 = __expf(m0r - mn0), a1 = __expf(m1r - mn1);
        m0r = mn0; m1r = mn1;

        float s0 = 0.f, s1 = 0.f;
        uint32_t ph[4][4], pl[4][4];
#pragma unroll
        for (int nf = 0; nf < 8; nf++) {
            float e0 = __expf(S[nf][0] - mn0);
            float e1 = __expf(S[nf][1] - mn0);
            float e2 = __expf(S[nf][2] - mn1);
            float e3 = __expf(S[nf][3] - mn1);
            s0 += e0 + e1; s1 += e2 + e3;
            __nv_bfloat16 h0 = __float2bfloat16(e0);
            __nv_bfloat16 h1 = __float2bfloat16(e1);
            __nv_bfloat16 h2 = __float2bfloat16(e2);
            __nv_bfloat16 h3 = __float2bfloat16(e3);
            __nv_bfloat16 g0 = __float2bfloat16(e0 - __bfloat162float(h0));
            __nv_bfloat16 g1 = __float2bfloat16(e1 - __bfloat162float(h1));
            __nv_bfloat16 g2 = __float2bfloat16(e2 - __bfloat162float(h2));
            __nv_bfloat16 g3 = __float2bfloat16(e3 - __bfloat162float(h3));
            int kf = nf >> 1;
            if ((nf & 1) == 0) {
                ph[kf][0] = pk2(h0, h1); ph[kf][1] = pk2(h2, h3);
                pl[kf][0] = pk2(g0, g1); pl[kf][1] = pk2(g2, g3);
            } else {
                ph[kf][2] = pk2(h0, h1); ph[kf][3] = pk2(h2, h3);
                pl[kf][2] = pk2(g0, g1); pl[kf][3] = pk2(g2, g3);
            }
        }
        s0 += __shfl_xor_sync(0xffffffffu, s0, 1);
        s0 += __shfl_xor_sync(0xffffffffu, s0, 2);
        s1 += __shfl_xor_sync(0xffffffffu, s1, 1);
        s1 += __shfl_xor_sync(0xffffffffu, s1, 2);
        l0r = l0r * a0 + s0;
        l1r = l1r * a1 + s1;
#pragma unroll
        for (int nf = 0; nf < 8; nf++) {
            O[nf][0] *= a0; O[nf][1] *= a0;
            O[nf][2] *= a1; O[nf][3] *= a1;
        }

        // ---- O += P V (bf16x3). V natural [key][d]; B-frag via u16 gathers ----
#pragma unroll
        for (int kf = 0; kf < 4; kf++) {
            int kb = kf * 16 + qt * 2;
#pragma unroll
            for (int nf = 0; nf < 8; nf++) {
                int d = nf * 8 + gr;
                uint32_t vbh[2], vbl[2];
                {
                    uint32_t x0 = *(const unsigned short*)(cVh + kb * AROW + d * 2);
                    uint32_t x1 = *(const unsigned short*)(cVh + (kb + 1) * AROW + d * 2);
                    uint32_t x2 = *(const unsigned short*)(cVh + (kb + 8) * AROW + d * 2);
                    uint32_t x3 = *(const unsigned short*)(cVh + (kb + 9) * AROW + d * 2);
                    vbh[0] = x0 | (x1 << 16);
                    vbh[1] = x2 | (x3 << 16);
                }
                {
                    uint32_t x0 = *(const unsigned short*)(cVl + kb * AROW + d * 2);
                    uint32_t x1 = *(const unsigned short*)(cVl + (kb + 1) * AROW + d * 2);
                    uint32_t x2 = *(const unsigned short*)(cVl + (kb + 8) * AROW + d * 2);
                    uint32_t x3 = *(const unsigned short*)(cVl + (kb + 9) * AROW + d * 2);
                    vbl[0] = x0 | (x1 << 16);
                    vbl[1] = x2 | (x3 << 16);
                }
                mma_bf16(O[nf], ph[kf], vbh);
                mma_bf16(O[nf], ph[kf], vbl);
                mma_bf16(O[nf], pl[kf], vbh);
            }
        }

        __syncthreads();
        if (kt + 2 < 32) fill(kt & 1, (kt + 2) * 64);
    }

    // ---- epilogue ----
    float inv0 = 1.0f / l0r, inv1 = 1.0f / l1r;
    int b = bh >> 3, h = bh & 7;
#pragma unroll
    for (int nf = 0; nf < 8; nf++) {
        int d = nf * 8 + qt * 2;
        float2 o0 = make_float2(O[nf][0] * inv0, O[nf][1] * inv0);
        float2 o1 = make_float2(O[nf][2] * inv1, O[nf][3] * inv1);
        *(float2*)&out[((size_t)(b * SS) + r0) * HD + h * 64 + d]       = o0;
        *(float2*)&out[((size_t)(b * SS) + r0 + 8) * HD + h * 64 + d]   = o1;
    }
}

// ---------------------------------------------------------------------------
extern "C" void kernel_launch(void* const* d_in, const int* in_sizes, int n_in,
                              void* d_out, int out_size)
{
    const float* x  = (const float*)d_in[0];
    const float* Wq = (const float*)d_in[1];
    const float* bq = (const float*)d_in[2];
    const float* Wk = (const float*)d_in[3];
    const float* bk = (const float*)d_in[4];
    const float* Wv = (const float*)d_in[5];
    const float* bv = (const float*)d_in[6];
    const float* ah = (const float*)d_in[7];
    const float* vh = (const float*)d_in[8];
    float* out = (float*)d_out;

    zhat_kernel<<<SS / 256, 256>>>(ah, vh);
    split_kernel<<<(NX4 + NW4) / 256, 256>>>(x, Wq, Wk, Wv);

    cudaFuncSetAttribute(proj_mma,
                         cudaFuncAttributeMaxDynamicSharedMemorySize, PROJ_SMEM);
    proj_mma<<<dim3(12, 64), 256, PROJ_SMEM>>>(bq, bk, bv, nullptr);

    cudaFuncSetAttribute(attn_mma,
                         cudaFuncAttributeMaxDynamicSharedMemorySize, ATTN_SMEM);
    attn_mma<<<dim3(SS / 128, BB * HH), 256, ATTN_SMEM>>>(out);
}

// round 4
// speedup vs baseline: 2.6593x; 1.1828x over previous
#include <cuda_runtime.h>
#include <cuda_bf16.h>
#include <math.h>
#include <stdint.h>

#define BB 4
#define SS 2048
#define FF 512
#define HH 8
#define DD 64
#define HD 512
#define MT (BB*SS)   // 8192

// ---------------------------------------------------------------------------
// Scratch (static device globals = sanctioned scratch path)
// ---------------------------------------------------------------------------
__device__ __nv_bfloat16 g_Xh[MT*FF];
__device__ __nv_bfloat16 g_Xl[MT*FF];
__device__ __nv_bfloat16 g_Wh[3*HD*FF];
__device__ __nv_bfloat16 g_Wl[3*HD*FF];
__device__ __nv_bfloat16 g_Qh[BB*HH*SS*DD];
__device__ __nv_bfloat16 g_Ql[BB*HH*SS*DD];
__device__ __nv_bfloat16 g_Kh[BB*HH*SS*DD];
__device__ __nv_bfloat16 g_Kl[BB*HH*SS*DD];
__device__ __nv_bfloat16 g_Vth[BB*HH*DD*SS];   // transposed: [b,h,d,s]
__device__ __nv_bfloat16 g_Vtl[BB*HH*DD*SS];   // transposed: [b,h,d,s]
__device__ float g_zt[SS];

// ---------------------------------------------------------------------------
// Helpers
// ---------------------------------------------------------------------------
__device__ __forceinline__ uint32_t smem_u32(const void* p) {
    uint32_t a;
    asm("{ .reg .u64 t; cvta.to.shared.u64 t, %1; cvt.u32.u64 %0, t; }"
        : "=r"(a) : "l"(p));
    return a;
}

#define CP_ASYNC16(dst, src) \
    asm volatile("cp.async.cg.shared.global [%0], [%1], 16;" \
        :: "r"(dst), "l"(src) : "memory")
#define CP_COMMIT() asm volatile("cp.async.commit_group;" ::: "memory")
#define CP_WAIT1()  asm volatile("cp.async.wait_group 1;" ::: "memory")

// D += A * B  (m16n8k16, bf16 inputs, fp32 accumulate)
__device__ __forceinline__ void mma_bf16(float* d, const uint32_t* a, const uint32_t* b) {
    asm volatile(
        "mma.sync.aligned.m16n8k16.row.col.f32.bf16.bf16.f32 "
        "{%0,%1,%2,%3}, {%4,%5,%6,%7}, {%8,%9}, {%0,%1,%2,%3};"
        : "+f"(d[0]), "+f"(d[1]), "+f"(d[2]), "+f"(d[3])
        : "r"(a[0]), "r"(a[1]), "r"(a[2]), "r"(a[3]), "r"(b[0]), "r"(b[1]));
}

__device__ __forceinline__ uint32_t pk2(__nv_bfloat16 a, __nv_bfloat16 b) {
    return (uint32_t)__bfloat16_as_ushort(a) | ((uint32_t)__bfloat16_as_ushort(b) << 16);
}

// ---------------------------------------------------------------------------
// z_hat table
// ---------------------------------------------------------------------------
__global__ void zhat_kernel(const float* __restrict__ ah, const float* __restrict__ vh)
{
    int i = blockIdx.x * blockDim.x + threadIdx.x;
    if (i < SS) {
        float a = ah[0], v = vh[0];
        float z = 1.0f + expf(v) / (1.0f + expf(v - a * (float)i));
        g_zt[i] = z * 0.125f;   // includes 1/sqrt(64)
    }
}

// ---------------------------------------------------------------------------
// Split X and W (fp32 -> bf16 hi + bf16 lo)
// ---------------------------------------------------------------------------
#define NX4 (MT*FF/4)          // 1048576 float4
#define NW4 (3*HD*FF/4)        // 196608 float4
#define NW4_1 (HD*FF/4)        // 65536

__global__ __launch_bounds__(256) void split_kernel(
    const float* __restrict__ X, const float* __restrict__ Wq,
    const float* __restrict__ Wk, const float* __restrict__ Wv)
{
    int i = blockIdx.x * 256 + threadIdx.x;
    const float* src;
    __nv_bfloat16 *dh, *dl;
    int off;
    if (i < NX4) {
        src = X; off = i; dh = g_Xh; dl = g_Xl;
    } else {
        int j = i - NX4;
        if (j < NW4_1)            { src = Wq; off = j; }
        else if (j < 2 * NW4_1)   { src = Wk; off = j - NW4_1; }
        else                      { src = Wv; off = j - 2 * NW4_1; }
        dh = g_Wh + (size_t)(j / NW4_1) * HD * FF;
        dl = g_Wl + (size_t)(j / NW4_1) * HD * FF;
    }
    float4 v = ((const float4*)src)[off];
    float vv[4] = {v.x, v.y, v.z, v.w};
    __nv_bfloat16 h[4], l[4];
#pragma unroll
    for (int k = 0; k < 4; k++) {
        h[k] = __float2bfloat16(vv[k]);
        l[k] = __float2bfloat16(vv[k] - __bfloat162float(h[k]));
    }
    size_t o4 = (size_t)off * 4;
    *(__nv_bfloat162*)&dh[o4]     = *(__nv_bfloat162*)&h[0];
    *(__nv_bfloat162*)&dh[o4 + 2] = *(__nv_bfloat162*)&h[2];
    *(__nv_bfloat162*)&dl[o4]     = *(__nv_bfloat162*)&l[0];
    *(__nv_bfloat162*)&dl[o4 + 2] = *(__nv_bfloat162*)&l[2];
}

// ---------------------------------------------------------------------------
// Fused QKV projection via mma.sync, bf16x3 split.
// CTA: 128 m-rows x 128 n-cols. 256 threads = 8 warps stacked along m.
// V written transposed [b,h,d,s].
// ---------------------------------------------------------------------------
#define PROW 144
#define PARR 18432        // 128 rows * 144
#define PSTG (4*PARR)     // Xh,Xl,Wh,Wl
#define PROJ_SMEM (2*PSTG)

__global__ __launch_bounds__(256) void proj_mma(
    const float* __restrict__ bq, const float* __restrict__ bk,
    const float* __restrict__ bv)
{
    extern __shared__ char sm[];
    const int tid = threadIdx.x;
    const int w = tid >> 5, lane = tid & 31;
    const int gr = lane >> 2, qt = lane & 3;
    const int nb = blockIdx.x;          // 0..11
    const int m0 = blockIdx.y * 128;

    float acc[16][4];
#pragma unroll
    for (int i = 0; i < 16; i++)
#pragma unroll
        for (int j = 0; j < 4; j++) acc[i][j] = 0.f;

    auto fill = [&](int stg, int k0) {
        char* dstb = sm + stg * PSTG;
#pragma unroll
        for (int ii = 0; ii < 16; ii++) {
            int idx = ii * 256 + tid;
            int arr = idx >> 10;
            int r = (idx >> 3) & 127;
            int c = idx & 7;
            const __nv_bfloat16* src;
            if (arr == 0)      src = g_Xh + (size_t)(m0 + r) * FF + k0 + c * 8;
            else if (arr == 1) src = g_Xl + (size_t)(m0 + r) * FF + k0 + c * 8;
            else if (arr == 2) src = g_Wh + (size_t)(nb * 128 + r) * FF + k0 + c * 8;
            else               src = g_Wl + (size_t)(nb * 128 + r) * FF + k0 + c * 8;
            uint32_t d = smem_u32(dstb + arr * PARR + r * PROW + c * 16);
            CP_ASYNC16(d, src);
        }
        CP_COMMIT();
    };

    fill(0, 0);
    fill(1, 64);

    const int arow = w * 16 + gr;
#pragma unroll 1
    for (int ks = 0; ks < 8; ks++) {
        CP_WAIT1();
        __syncthreads();
        const char* B  = sm + (ks & 1) * PSTG;
        const char* Xh = B;
        const char* Xl = B + PARR;
        const char* Wh = B + 2 * PARR;
        const char* Wl = B + 3 * PARR;
#pragma unroll
        for (int kf = 0; kf < 4; kf++) {
            int ao = arow * PROW + kf * 32 + qt * 4;
            uint32_t ah[4], al[4];
            ah[0] = *(const uint32_t*)(Xh + ao);
            ah[1] = *(const uint32_t*)(Xh + ao + 8 * PROW);
            ah[2] = *(const uint32_t*)(Xh + ao + 16);
            ah[3] = *(const uint32_t*)(Xh + ao + 8 * PROW + 16);
            al[0] = *(const uint32_t*)(Xl + ao);
            al[1] = *(const uint32_t*)(Xl + ao + 8 * PROW);
            al[2] = *(const uint32_t*)(Xl + ao + 16);
            al[3] = *(const uint32_t*)(Xl + ao + 8 * PROW + 16);
#pragma unroll
            for (int nf = 0; nf < 16; nf++) {
                int bo = (nf * 8 + gr) * PROW + kf * 32 + qt * 4;
                uint32_t bh[2], bl[2];
                bh[0] = *(const uint32_t*)(Wh + bo);
                bh[1] = *(const uint32_t*)(Wh + bo + 16);
                bl[0] = *(const uint32_t*)(Wl + bo);
                bl[1] = *(const uint32_t*)(Wl + bo + 16);
                mma_bf16(acc[nf], ah, bh);
                mma_bf16(acc[nf], ah, bl);
                mma_bf16(acc[nf], al, bh);
            }
        }
        __syncthreads();
        if (ks + 2 < 8) fill(ks & 1, (ks + 2) * 64);
    }

    // epilogue: add bias, split hi/lo. Q/K -> [b,h,s,d], V -> [b,h,d,s]
    const int r0 = m0 + w * 16 + gr;
#pragma unroll
    for (int nf = 0; nf < 16; nf++) {
        int ng = nb * 128 + nf * 8 + qt * 2;
        int sel = ng >> 9;
        int within = ng & 511;
        const float* bias = (sel == 0) ? bq : (sel == 1) ? bk : bv;
        float b0 = bias[within], b1 = bias[within + 1];
        int h = within >> 6, d = within & 63;
#pragma unroll
        for (int half = 0; half < 2; half++) {
            int m = r0 + half * 8;
            int bb = m >> 11, s = m & 2047;
            float y0 = acc[nf][half * 2 + 0] + b0;
            float y1 = acc[nf][half * 2 + 1] + b1;
            __nv_bfloat16 h0 = __float2bfloat16(y0);
            __nv_bfloat16 h1 = __float2bfloat16(y1);
            __nv_bfloat16 l0 = __float2bfloat16(y0 - __bfloat162float(h0));
            __nv_bfloat16 l1 = __float2bfloat16(y1 - __bfloat162float(h1));
            if (sel < 2) {
                __nv_bfloat16* dh = (sel == 0) ? g_Qh : g_Kh;
                __nv_bfloat16* dl = (sel == 0) ? g_Ql : g_Kl;
                size_t a = (((size_t)(bb * HH + h)) * SS + s) * DD + d;
                *(uint32_t*)&dh[a] = pk2(h0, h1);
                *(uint32_t*)&dl[a] = pk2(l0, l1);
            } else {
                size_t a0 = (((size_t)(bb * HH + h)) * DD + d) * SS + s;
                size_t a1 = a0 + SS;
                g_Vth[a0] = h0; g_Vth[a1] = h1;
                g_Vtl[a0] = l0; g_Vtl[a1] = l1;
            }
        }
    }
}

// ---------------------------------------------------------------------------
// Flash attention via mma.sync, bf16x3, register softmax.
// CTA: 128 q-rows (8 warps x m16), key tiles of 64, cp.async double buffer.
// K smem [key][d]; V smem transposed [d][key] -> PV B-frags are 2x LDS32.
// 2 CTAs/SM via launch_bounds reg cap.
// ---------------------------------------------------------------------------
#define AROW 144
#define AARR 9216         // 64 rows * 144
#define ASTG (4*AARR)     // Kh,Kl,Vth,Vtl
#define AZT  (2*ASTG)
#define ATTN_SMEM (AZT + SS*4)

__global__ __launch_bounds__(256, 2) void attn_mma(float* __restrict__ out)
{
    extern __shared__ char sm[];
    float* zts = (float*)(sm + AZT);
    const int tid = threadIdx.x;
    const int w = tid >> 5, lane = tid & 31;
    const int gr = lane >> 2, qt = lane & 3;
    const int bh = blockIdx.y;
    const int q0 = blockIdx.x * 128;

    for (int i = tid; i < SS; i += 256) zts[i] = g_zt[i];

    // Q fragments straight from gmem (once)
    const int r0 = q0 + w * 16 + gr;
    const __nv_bfloat16* Qh = g_Qh + (size_t)bh * SS * DD;
    const __nv_bfloat16* Ql = g_Ql + (size_t)bh * SS * DD;
    uint32_t qah[4][4], qal[4][4];
#pragma unroll
    for (int kf = 0; kf < 4; kf++) {
        int col = kf * 16 + qt * 2;
        qah[kf][0] = *(const uint32_t*)(Qh + (size_t)r0 * 64 + col);
        qah[kf][1] = *(const uint32_t*)(Qh + (size_t)(r0 + 8) * 64 + col);
        qah[kf][2] = *(const uint32_t*)(Qh + (size_t)r0 * 64 + col + 8);
        qah[kf][3] = *(const uint32_t*)(Qh + (size_t)(r0 + 8) * 64 + col + 8);
        qal[kf][0] = *(const uint32_t*)(Ql + (size_t)r0 * 64 + col);
        qal[kf][1] = *(const uint32_t*)(Ql + (size_t)(r0 + 8) * 64 + col);
        qal[kf][2] = *(const uint32_t*)(Ql + (size_t)r0 * 64 + col + 8);
        qal[kf][3] = *(const uint32_t*)(Ql + (size_t)(r0 + 8) * 64 + col + 8);
    }

    auto fill = [&](int stg, int k0) {
        char* dstb = sm + stg * ASTG;
#pragma unroll
        for (int ii = 0; ii < 8; ii++) {
            int idx = ii * 256 + tid;
            int arr = idx >> 9;
            int r = (idx >> 3) & 63;
            int c = idx & 7;
            const __nv_bfloat16* src;
            if (arr == 0)      src = g_Kh + ((size_t)bh * SS + k0 + r) * 64 + c * 8;
            else if (arr == 1) src = g_Kl + ((size_t)bh * SS + k0 + r) * 64 + c * 8;
            else if (arr == 2) src = g_Vth + ((size_t)bh * DD + r) * SS + k0 + c * 8;
            else               src = g_Vtl + ((size_t)bh * DD + r) * SS + k0 + c * 8;
            uint32_t d = smem_u32(dstb + arr * AARR + r * AROW + c * 16);
            CP_ASYNC16(d, src);
        }
        CP_COMMIT();
    };

    fill(0, 0);
    fill(1, 64);

    float O[8][4];
#pragma unroll
    for (int i = 0; i < 8; i++)
#pragma unroll
        for (int j = 0; j < 4; j++) O[i][j] = 0.f;
    float m0r = -1e30f, m1r = -1e30f, l0r = 0.f, l1r = 0.f;

#pragma unroll 1
    for (int kt = 0; kt < 32; kt++) {
        CP_WAIT1();
        __syncthreads();
        const char* B    = sm + (kt & 1) * ASTG;
        const char* cKh  = B;
        const char* cKl  = B + AARR;
        const char* cVth = B + 2 * AARR;
        const char* cVtl = B + 3 * AARR;
        const int k0 = kt * 64;

        // ---- S = Q K^T (bf16x3) ----
        float S[8][4];
#pragma unroll
        for (int i = 0; i < 8; i++)
#pragma unroll
            for (int j = 0; j < 4; j++) S[i][j] = 0.f;

#pragma unroll
        for (int kf = 0; kf < 4; kf++) {
#pragma unroll
            for (int nf = 0; nf < 8; nf++) {
                int bo = (nf * 8 + gr) * AROW + kf * 32 + qt * 4;
                uint32_t bhf[2], blf[2];
                bhf[0] = *(const uint32_t*)(cKh + bo);
                bhf[1] = *(const uint32_t*)(cKh + bo + 16);
                blf[0] = *(const uint32_t*)(cKl + bo);
                blf[1] = *(const uint32_t*)(cKl + bo + 16);
                mma_bf16(S[nf], qah[kf], bhf);
                mma_bf16(S[nf], qah[kf], blf);
                mma_bf16(S[nf], qal[kf], bhf);
            }
        }

        // ---- bias + online softmax (register fragments) ----
        float mt0 = -1e30f, mt1 = -1e30f;
#pragma unroll
        for (int nf = 0; nf < 8; nf++) {
            int c0 = k0 + nf * 8 + qt * 2;
            S[nf][0] *= zts[abs(r0 - c0)];
            S[nf][1] *= zts[abs(r0 - c0 - 1)];
            S[nf][2] *= zts[abs(r0 + 8 - c0)];
            S[nf][3] *= zts[abs(r0 + 8 - c0 - 1)];
            mt0 = fmaxf(mt0, fmaxf(S[nf][0], S[nf][1]));
            mt1 = fmaxf(mt1, fmaxf(S[nf][2], S[nf][3]));
        }
        mt0 = fmaxf(mt0, __shfl_xor_sync(0xffffffffu, mt0, 1));
        mt0 = fmaxf(mt0, __shfl_xor_sync(0xffffffffu, mt0, 2));
        mt1 = fmaxf(mt1, __shfl_xor_sync(0xffffffffu, mt1, 1));
        mt1 = fmaxf(mt1, __shfl_xor_sync(0xffffffffu, mt1, 2));
        float mn0 = fmaxf(m0r, mt0), mn1 = fmaxf(m1r, mt1);
        float a0 = __expf(m0r - mn0), a1 = __expf(m1r - mn1);
        m0r = mn0; m1r = mn1;

        float s0 = 0.f, s1 = 0.f;
        uint32_t ph[4][4], pl[4][4];
#pragma unroll
        for (int nf = 0; nf < 8; nf++) {
            float e0 = __expf(S[nf][0] - mn0);
            float e1 = __expf(S[nf][1] - mn0);
            float e2 = __expf(S[nf][2] - mn1);
            float e3 = __expf(S[nf][3] - mn1);
            s0 += e0 + e1; s1 += e2 + e3;
            __nv_bfloat16 h0 = __float2bfloat16(e0);
            __nv_bfloat16 h1 = __float2bfloat16(e1);
            __nv_bfloat16 h2 = __float2bfloat16(e2);
            __nv_bfloat16 h3 = __float2bfloat16(e3);
            __nv_bfloat16 g0 = __float2bfloat16(e0 - __bfloat162float(h0));
            __nv_bfloat16 g1 = __float2bfloat16(e1 - __bfloat162float(h1));
            __nv_bfloat16 g2 = __float2bfloat16(e2 - __bfloat162float(h2));
            __nv_bfloat16 g3 = __float2bfloat16(e3 - __bfloat162float(h3));
            int kf = nf >> 1;
            if ((nf & 1) == 0) {
                ph[kf][0] = pk2(h0, h1); ph[kf][1] = pk2(h2, h3);
                pl[kf][0] = pk2(g0, g1); pl[kf][1] = pk2(g2, g3);
            } else {
                ph[kf][2] = pk2(h0, h1); ph[kf][3] = pk2(h2, h3);
                pl[kf][2] = pk2(g0, g1); pl[kf][3] = pk2(g2, g3);
            }
        }
        s0 += __shfl_xor_sync(0xffffffffu, s0, 1);
        s0 += __shfl_xor_sync(0xffffffffu, s0, 2);
        s1 += __shfl_xor_sync(0xffffffffu, s1, 1);
        s1 += __shfl_xor_sync(0xffffffffu, s1, 2);
        l0r = l0r * a0 + s0;
        l1r = l1r * a1 + s1;
#pragma unroll
        for (int nf = 0; nf < 8; nf++) {
            O[nf][0] *= a0; O[nf][1] *= a0;
            O[nf][2] *= a1; O[nf][3] *= a1;
        }

        // ---- O += P V (bf16x3). V^T smem [d][key] -> direct 32-bit B frags ----
#pragma unroll
        for (int kf = 0; kf < 4; kf++) {
            int kb = (kf * 16 + qt * 2) * 2;   // byte offset of key pair
#pragma unroll
            for (int nf = 0; nf < 8; nf++) {
                int drow = (nf * 8 + gr) * AROW;
                uint32_t vbh[2], vbl[2];
                vbh[0] = *(const uint32_t*)(cVth + drow + kb);
                vbh[1] = *(const uint32_t*)(cVth + drow + kb + 16);
                vbl[0] = *(const uint32_t*)(cVtl + drow + kb);
                vbl[1] = *(const uint32_t*)(cVtl + drow + kb + 16);
                mma_bf16(O[nf], ph[kf], vbh);
                mma_bf16(O[nf], ph[kf], vbl);
                mma_bf16(O[nf], pl[kf], vbh);
            }
        }

        __syncthreads();
        if (kt + 2 < 32) fill(kt & 1, (kt + 2) * 64);
    }

    // ---- epilogue ----
    float inv0 = 1.0f / l0r, inv1 = 1.0f / l1r;
    int b = bh >> 3, h = bh & 7;
#pragma unroll
    for (int nf = 0; nf < 8; nf++) {
        int d = nf * 8 + qt * 2;
        float2 o0 = make_float2(O[nf][0] * inv0, O[nf][1] * inv0);
        float2 o1 = make_float2(O[nf][2] * inv1, O[nf][3] * inv1);
        *(float2*)&out[((size_t)(b * SS) + r0) * HD + h * 64 + d]       = o0;
        *(float2*)&out[((size_t)(b * SS) + r0 + 8) * HD + h * 64 + d]   = o1;
    }
}

// ---------------------------------------------------------------------------
extern "C" void kernel_launch(void* const* d_in, const int* in_sizes, int n_in,
                              void* d_out, int out_size)
{
    const float* x  = (const float*)d_in[0];
    const float* Wq = (const float*)d_in[1];
    const float* bq = (const float*)d_in[2];
    const float* Wk = (const float*)d_in[3];
    const float* bk = (const float*)d_in[4];
    const float* Wv = (const float*)d_in[5];
    const float* bv = (const float*)d_in[6];
    const float* ah = (const float*)d_in[7];
    const float* vh = (const float*)d_in[8];
    float* out = (float*)d_out;

    zhat_kernel<<<SS / 256, 256>>>(ah, vh);
    split_kernel<<<(NX4 + NW4) / 256, 256>>>(x, Wq, Wk, Wv);

    cudaFuncSetAttribute(proj_mma,
                         cudaFuncAttributeMaxDynamicSharedMemorySize, PROJ_SMEM);
    proj_mma<<<dim3(12, 64), 256, PROJ_SMEM>>>(bq, bk, bv);

    cudaFuncSetAttribute(attn_mma,
                         cudaFuncAttributeMaxDynamicSharedMemorySize, ATTN_SMEM);
    attn_mma<<<dim3(SS / 128, BB * HH), 256, ATTN_SMEM>>>(out);
}

// round 6
// speedup vs baseline: 2.8117x; 1.0573x over previous
#include <cuda_runtime.h>
#include <cuda_bf16.h>
#include <math.h>
#include <stdint.h>

#define BB 4
#define SS 2048
#define FF 512
#define HH 8
#define DD 64
#define HD 512
#define MT (BB*SS)   // 8192

// ---------------------------------------------------------------------------
// Scratch (static device globals = sanctioned scratch path)
// ---------------------------------------------------------------------------
__device__ __nv_bfloat16 g_Xh[MT*FF];
__device__ __nv_bfloat16 g_Xl[MT*FF];
__device__ __nv_bfloat16 g_Wh[3*HD*FF];
__device__ __nv_bfloat16 g_Wl[3*HD*FF];
__device__ __nv_bfloat16 g_Qh[BB*HH*SS*DD];
__device__ __nv_bfloat16 g_Ql[BB*HH*SS*DD];
__device__ __nv_bfloat16 g_Kh[BB*HH*SS*DD];
__device__ __nv_bfloat16 g_Kl[BB*HH*SS*DD];
__device__ __nv_bfloat16 g_Vth[BB*HH*DD*SS];   // transposed: [b,h,d,s]
__device__ __nv_bfloat16 g_Vtl[BB*HH*DD*SS];   // transposed: [b,h,d,s]
__device__ float g_zt[SS];

// ---------------------------------------------------------------------------
// Helpers
// ---------------------------------------------------------------------------
__device__ __forceinline__ uint32_t smem_u32(const void* p) {
    uint32_t a;
    asm("{ .reg .u64 t; cvta.to.shared.u64 t, %1; cvt.u32.u64 %0, t; }"
        : "=r"(a) : "l"(p));
    return a;
}

#define CP_ASYNC16(dst, src) \
    asm volatile("cp.async.cg.shared.global [%0], [%1], 16;" \
        :: "r"(dst), "l"(src) : "memory")
#define CP_COMMIT() asm volatile("cp.async.commit_group;" ::: "memory")
#define CP_WAIT1()  asm volatile("cp.async.wait_group 1;" ::: "memory")

// D += A * B  (m16n8k16, bf16 inputs, fp32 accumulate)
__device__ __forceinline__ void mma_bf16(float* d, const uint32_t* a, const uint32_t* b) {
    asm volatile(
        "mma.sync.aligned.m16n8k16.row.col.f32.bf16.bf16.f32 "
        "{%0,%1,%2,%3}, {%4,%5,%6,%7}, {%8,%9}, {%0,%1,%2,%3};"
        : "+f"(d[0]), "+f"(d[1]), "+f"(d[2]), "+f"(d[3])
        : "r"(a[0]), "r"(a[1]), "r"(a[2]), "r"(a[3]), "r"(b[0]), "r"(b[1]));
}

// ldmatrix x4 (non-transposed)
__device__ __forceinline__ void ldsm4(uint32_t* r, uint32_t addr) {
    asm volatile("ldmatrix.sync.aligned.m8n8.x4.shared.b16 {%0,%1,%2,%3}, [%4];"
        : "=r"(r[0]), "=r"(r[1]), "=r"(r[2]), "=r"(r[3]) : "r"(addr));
}

__device__ __forceinline__ uint32_t pk2(__nv_bfloat16 a, __nv_bfloat16 b) {
    return (uint32_t)__bfloat16_as_ushort(a) | ((uint32_t)__bfloat16_as_ushort(b) << 16);
}

// ---------------------------------------------------------------------------
// z_hat table
// ---------------------------------------------------------------------------
__global__ void zhat_kernel(const float* __restrict__ ah, const float* __restrict__ vh)
{
    int i = blockIdx.x * blockDim.x + threadIdx.x;
    if (i < SS) {
        float a = ah[0], v = vh[0];
        float z = 1.0f + expf(v) / (1.0f + expf(v - a * (float)i));
        g_zt[i] = z * 0.125f;   // includes 1/sqrt(64)
    }
}

// ---------------------------------------------------------------------------
// Split X and W (fp32 -> bf16 hi + bf16 lo)
// ---------------------------------------------------------------------------
#define NX4 (MT*FF/4)          // 1048576 float4
#define NW4 (3*HD*FF/4)        // 196608 float4
#define NW4_1 (HD*FF/4)        // 65536

__global__ __launch_bounds__(256) void split_kernel(
    const float* __restrict__ X, const float* __restrict__ Wq,
    const float* __restrict__ Wk, const float* __restrict__ Wv)
{
    int i = blockIdx.x * 256 + threadIdx.x;
    const float* src;
    __nv_bfloat16 *dh, *dl;
    int off;
    if (i < NX4) {
        src = X; off = i; dh = g_Xh; dl = g_Xl;
    } else {
        int j = i - NX4;
        if (j < NW4_1)            { src = Wq; off = j; }
        else if (j < 2 * NW4_1)   { src = Wk; off = j - NW4_1; }
        else                      { src = Wv; off = j - 2 * NW4_1; }
        dh = g_Wh + (size_t)(j / NW4_1) * HD * FF;
        dl = g_Wl + (size_t)(j / NW4_1) * HD * FF;
    }
    float4 v = ((const float4*)src)[off];
    float vv[4] = {v.x, v.y, v.z, v.w};
    __nv_bfloat16 h[4], l[4];
#pragma unroll
    for (int k = 0; k < 4; k++) {
        h[k] = __float2bfloat16(vv[k]);
        l[k] = __float2bfloat16(vv[k] - __bfloat162float(h[k]));
    }
    size_t o4 = (size_t)off * 4;
    *(__nv_bfloat162*)&dh[o4]     = *(__nv_bfloat162*)&h[0];
    *(__nv_bfloat162*)&dh[o4 + 2] = *(__nv_bfloat162*)&h[2];
    *(__nv_bfloat162*)&dl[o4]     = *(__nv_bfloat162*)&l[0];
    *(__nv_bfloat162*)&dl[o4 + 2] = *(__nv_bfloat162*)&l[2];
}

// ---------------------------------------------------------------------------
// Fused QKV projection via mma.sync + ldmatrix, bf16x3 split.
// CTA: 128 m-rows x 128 n-cols. 256 threads = 8 warps stacked along m.
// ---------------------------------------------------------------------------
#define PROW 144
#define PARR 18432        // 128 rows * 144
#define PSTG (4*PARR)     // Xh,Xl,Wh,Wl
#define PROJ_SMEM (2*PSTG)

__global__ __launch_bounds__(256) void proj_mma(
    const float* __restrict__ bq, const float* __restrict__ bk,
    const float* __restrict__ bv)
{
    extern __shared__ char sm[];
    const uint32_t sbase = smem_u32(sm);
    const int tid = threadIdx.x;
    const int w = tid >> 5, lane = tid & 31;
    const int gr = lane >> 2, qt = lane & 3;
    const int nb = blockIdx.x;          // 0..11
    const int m0 = blockIdx.y * 128;

    // ldmatrix per-lane offsets
    const uint32_t rowoffB = (uint32_t)(((lane & 7) + ((lane >> 4) << 3)) * PROW
                                        + ((lane >> 3) & 1) * 16);
    const uint32_t rowoffA = (uint32_t)(((lane & 7) + (((lane >> 3) & 1) << 3)) * PROW
                                        + (lane >> 4) * 16);

    float acc[16][4];
#pragma unroll
    for (int i = 0; i < 16; i++)
#pragma unroll
        for (int j = 0; j < 4; j++) acc[i][j] = 0.f;

    auto fill = [&](int stg, int k0) {
        char* dstb = sm + stg * PSTG;
#pragma unroll
        for (int ii = 0; ii < 16; ii++) {
            int idx = ii * 256 + tid;
            int arr = idx >> 10;
            int r = (idx >> 3) & 127;
            int c = idx & 7;
            const __nv_bfloat16* src;
            if (arr == 0)      src = g_Xh + (size_t)(m0 + r) * FF + k0 + c * 8;
            else if (arr == 1) src = g_Xl + (size_t)(m0 + r) * FF + k0 + c * 8;
            else if (arr == 2) src = g_Wh + (size_t)(nb * 128 + r) * FF + k0 + c * 8;
            else               src = g_Wl + (size_t)(nb * 128 + r) * FF + k0 + c * 8;
            uint32_t d = smem_u32(dstb + arr * PARR + r * PROW + c * 16);
            CP_ASYNC16(d, src);
        }
        CP_COMMIT();
    };

    fill(0, 0);
    fill(1, 64);

    const uint32_t w16off = (uint32_t)(w * 16 * PROW);
#pragma unroll 1
    for (int ks = 0; ks < 8; ks++) {
        CP_WAIT1();
        __syncthreads();
        const uint32_t B   = sbase + (ks & 1) * PSTG;
        const uint32_t aXh = B;
        const uint32_t aXl = B + PARR;
        const uint32_t aWh = B + 2 * PARR;
        const uint32_t aWl = B + 3 * PARR;
#pragma unroll
        for (int kf = 0; kf < 4; kf++) {
            uint32_t xh[4], xl[4];
            ldsm4(xh, aXh + w16off + kf * 32 + rowoffA);
            ldsm4(xl, aXl + w16off + kf * 32 + rowoffA);
#pragma unroll
            for (int nfp = 0; nfp < 8; nfp++) {
                uint32_t wh4[4], wl4[4];
                ldsm4(wh4, aWh + nfp * (16 * PROW) + kf * 32 + rowoffB);
                ldsm4(wl4, aWl + nfp * (16 * PROW) + kf * 32 + rowoffB);
                mma_bf16(acc[2 * nfp],     xh, &wh4[0]);
                mma_bf16(acc[2 * nfp],     xh, &wl4[0]);
                mma_bf16(acc[2 * nfp],     xl, &wh4[0]);
                mma_bf16(acc[2 * nfp + 1], xh, &wh4[2]);
                mma_bf16(acc[2 * nfp + 1], xh, &wl4[2]);
                mma_bf16(acc[2 * nfp + 1], xl, &wh4[2]);
            }
        }
        __syncthreads();
        if (ks + 2 < 8) fill(ks & 1, (ks + 2) * 64);
    }

    // epilogue: add bias, split hi/lo. Q/K -> [b,h,s,d], V -> [b,h,d,s]
    const int r0 = m0 + w * 16 + gr;
#pragma unroll
    for (int nf = 0; nf < 16; nf++) {
        int ng = nb * 128 + nf * 8 + qt * 2;
        int sel = ng >> 9;
        int within = ng & 511;
        const float* bias = (sel == 0) ? bq : (sel == 1) ? bk : bv;
        float b0 = bias[within], b1 = bias[within + 1];
        int h = within >> 6, d = within & 63;
#pragma unroll
        for (int half = 0; half < 2; half++) {
            int m = r0 + half * 8;
            int bb = m >> 11, s = m & 2047;
            float y0 = acc[nf][half * 2 + 0] + b0;
            float y1 = acc[nf][half * 2 + 1] + b1;
            __nv_bfloat16 h0 = __float2bfloat16(y0);
            __nv_bfloat16 h1 = __float2bfloat16(y1);
            __nv_bfloat16 l0 = __float2bfloat16(y0 - __bfloat162float(h0));
            __nv_bfloat16 l1 = __float2bfloat16(y1 - __bfloat162float(h1));
            if (sel < 2) {
                __nv_bfloat16* dh = (sel == 0) ? g_Qh : g_Kh;
                __nv_bfloat16* dl = (sel == 0) ? g_Ql : g_Kl;
                size_t a = (((size_t)(bb * HH + h)) * SS + s) * DD + d;
                *(uint32_t*)&dh[a] = pk2(h0, h1);
                *(uint32_t*)&dl[a] = pk2(l0, l1);
            } else {
                size_t a0 = (((size_t)(bb * HH + h)) * DD + d) * SS + s;
                size_t a1 = a0 + SS;
                g_Vth[a0] = h0; g_Vth[a1] = h1;
                g_Vtl[a0] = l0; g_Vtl[a1] = l1;
            }
        }
    }
}

// ---------------------------------------------------------------------------
// Flash attention via mma.sync + ldmatrix, bf16x3, register softmax.
// CTA: 128 q-rows (8 warps x m16), key tiles of 64, cp.async double buffer.
// K smem [key][d]; V smem transposed [d][key]. 2 CTAs/SM.
// ---------------------------------------------------------------------------
#define AROW 144
#define AARR 9216         // 64 rows * 144
#define ASTG (4*AARR)     // Kh,Kl,Vth,Vtl
#define AZT  (2*ASTG)
#define ATTN_SMEM (AZT + SS*4)

__global__ __launch_bounds__(256, 2) void attn_mma(float* __restrict__ out)
{
    extern __shared__ char sm[];
    const uint32_t sbase = smem_u32(sm);
    float* zts = (float*)(sm + AZT);
    const int tid = threadIdx.x;
    const int w = tid >> 5, lane = tid & 31;
    const int gr = lane >> 2, qt = lane & 3;
    const int bh = blockIdx.y;
    const int q0 = blockIdx.x * 128;

    const uint32_t rowoffB = (uint32_t)(((lane & 7) + ((lane >> 4) << 3)) * AROW
                                        + ((lane >> 3) & 1) * 16);

    for (int i = tid; i < SS; i += 256) zts[i] = g_zt[i];

    // Q fragments straight from gmem (once)
    const int r0 = q0 + w * 16 + gr;
    const __nv_bfloat16* Qh = g_Qh + (size_t)bh * SS * DD;
    const __nv_bfloat16* Ql = g_Ql + (size_t)bh * SS * DD;
    uint32_t qah[4][4], qal[4][4];
#pragma unroll
    for (int kf = 0; kf < 4; kf++) {
        int col = kf * 16 + qt * 2;
        qah[kf][0] = *(const uint32_t*)(Qh + (size_t)r0 * 64 + col);
        qah[kf][1] = *(const uint32_t*)(Qh + (size_t)(r0 + 8) * 64 + col);
        qah[kf][2] = *(const uint32_t*)(Qh + (size_t)r0 * 64 + col + 8);
        qah[kf][3] = *(const uint32_t*)(Qh + (size_t)(r0 + 8) * 64 + col + 8);
        qal[kf][0] = *(const uint32_t*)(Ql + (size_t)r0 * 64 + col);
        qal[kf][1] = *(const uint32_t*)(Ql + (size_t)(r0 + 8) * 64 + col);
        qal[kf][2] = *(const uint32_t*)(Ql + (size_t)r0 * 64 + col + 8);
        qal[kf][3] = *(const uint32_t*)(Ql + (size_t)(r0 + 8) * 64 + col + 8);
    }

    auto fill = [&](int stg, int k0) {
        char* dstb = sm + stg * ASTG;
#pragma unroll
        for (int ii = 0; ii < 8; ii++) {
            int idx = ii * 256 + tid;
            int arr = idx >> 9;
            int r = (idx >> 3) & 63;
            int c = idx & 7;
            const __nv_bfloat16* src;
            if (arr == 0)      src = g_Kh + ((size_t)bh * SS + k0 + r) * 64 + c * 8;
            else if (arr == 1) src = g_Kl + ((size_t)bh * SS + k0 + r) * 64 + c * 8;
            else if (arr == 2) src = g_Vth + ((size_t)bh * DD + r) * SS + k0 + c * 8;
            else               src = g_Vtl + ((size_t)bh * DD + r) * SS + k0 + c * 8;
            uint32_t d = smem_u32(dstb + arr * AARR + r * AROW + c * 16);
            CP_ASYNC16(d, src);
        }
        CP_COMMIT();
    };

    fill(0, 0);
    fill(1, 64);

    float O[8][4];
#pragma unroll
    for (int i = 0; i < 8; i++)
#pragma unroll
        for (int j = 0; j < 4; j++) O[i][j] = 0.f;
    float m0r = -1e30f, m1r = -1e30f, l0r = 0.f, l1r = 0.f;

#pragma unroll 1
    for (int kt = 0; kt < 32; kt++) {
        CP_WAIT1();
        __syncthreads();
        const uint32_t B    = sbase + (kt & 1) * ASTG;
        const uint32_t aKh  = B;
        const uint32_t aKl  = B + AARR;
        const uint32_t aVth = B + 2 * AARR;
        const uint32_t aVtl = B + 3 * AARR;
        const int k0 = kt * 64;

        // ---- S = Q K^T (bf16x3) via ldmatrix B-frags ----
        float S[8][4];
#pragma unroll
        for (int i = 0; i < 8; i++)
#pragma unroll
            for (int j = 0; j < 4; j++) S[i][j] = 0.f;

#pragma unroll
        for (int kf = 0; kf < 4; kf++) {
#pragma unroll
            for (int nfp = 0; nfp < 4; nfp++) {
                uint32_t rh[4], rl[4];
                ldsm4(rh, aKh + nfp * (16 * AROW) + kf * 32 + rowoffB);
                ldsm4(rl, aKl + nfp * (16 * AROW) + kf * 32 + rowoffB);
                mma_bf16(S[2 * nfp],     qah[kf], &rh[0]);
                mma_bf16(S[2 * nfp],     qah[kf], &rl[0]);
                mma_bf16(S[2 * nfp],     qal[kf], &rh[0]);
                mma_bf16(S[2 * nfp + 1], qah[kf], &rh[2]);
                mma_bf16(S[2 * nfp + 1], qah[kf], &rl[2]);
                mma_bf16(S[2 * nfp + 1], qal[kf], &rh[2]);
            }
        }

        // ---- bias + online softmax (register fragments) ----
        float mt0 = -1e30f, mt1 = -1e30f;
#pragma unroll
        for (int nf = 0; nf < 8; nf++) {
            int c0 = k0 + nf * 8 + qt * 2;
            S[nf][0] *= zts[abs(r0 - c0)];
            S[nf][1] *= zts[abs(r0 - c0 - 1)];
            S[nf][2] *= zts[abs(r0 + 8 - c0)];
            S[nf][3] *= zts[abs(r0 + 8 - c0 - 1)];
            mt0 = fmaxf(mt0, fmaxf(S[nf][0], S[nf][1]));
            mt1 = fmaxf(mt1, fmaxf(S[nf][2], S[nf][3]));
        }
        mt0 = fmaxf(mt0, __shfl_xor_sync(0xffffffffu, mt0, 1));
        mt0 = fmaxf(mt0, __shfl_xor_sync(0xffffffffu, mt0, 2));
        mt1 = fmaxf(mt1, __shfl_xor_sync(0xffffffffu, mt1, 1));
        mt1 = fmaxf(mt1, __shfl_xor_sync(0xffffffffu, mt1, 2));
        float mn0 = fmaxf(m0r, mt0), mn1 = fmaxf(m1r, mt1);
        float a0 = __expf(m0r - mn0), a1 = __expf(m1r - mn1);
        m0r = mn0; m1r = mn1;

        float s0 = 0.f, s1 = 0.f;
        uint32_t ph[4][4], pl[4][4];
#pragma unroll
        for (int nf = 0; nf < 8; nf++) {
            float e0 = __expf(S[nf][0] - mn0);
            float e1 = __expf(S[nf][1] - mn0);
            float e2 = __expf(S[nf][2] - mn1);
            float e3 = __expf(S[nf][3] - mn1);
            s0 += e0 + e1; s1 += e2 + e3;
            __nv_bfloat16 h0 = __float2bfloat16(e0);
            __nv_bfloat16 h1 = __float2bfloat16(e1);
            __nv_bfloat16 h2 = __float2bfloat16(e2);
            __nv_bfloat16 h3 = __float2bfloat16(e3);
            __nv_bfloat16 g0 = __float2bfloat16(e0 - __bfloat162float(h0));
            __nv_bfloat16 g1 = __float2bfloat16(e1 - __bfloat162float(h1));
            __nv_bfloat16 g2 = __float2bfloat16(e2 - __bfloat162float(h2));
            __nv_bfloat16 g3 = __float2bfloat16(e3 - __bfloat162float(h3));
            int kf = nf >> 1;
            if ((nf & 1) == 0) {
                ph[kf][0] = pk2(h0, h1); ph[kf][1] = pk2(h2, h3);
                pl[kf][0] = pk2(g0, g1); pl[kf][1] = pk2(g2, g3);
            } else {
                ph[kf][2] = pk2(h0, h1); ph[kf][3] = pk2(h2, h3);
                pl[kf][2] = pk2(g0, g1); pl[kf][3] = pk2(g2, g3);
            }
        }
        s0 += __shfl_xor_sync(0xffffffffu, s0, 1);
        s0 += __shfl_xor_sync(0xffffffffu, s0, 2);
        s1 += __shfl_xor_sync(0xffffffffu, s1, 1);
        s1 += __shfl_xor_sync(0xffffffffu, s1, 2);
        l0r = l0r * a0 + s0;
        l1r = l1r * a1 + s1;
#pragma unroll
        for (int nf = 0; nf < 8; nf++) {
            O[nf][0] *= a0; O[nf][1] *= a0;
            O[nf][2] *= a1; O[nf][3] *= a1;
        }

        // ---- O += P V (bf16x3). V^T smem [d][key] via ldmatrix B-frags ----
#pragma unroll
        for (int kf = 0; kf < 4; kf++) {
#pragma unroll
            for (int nfp = 0; nfp < 4; nfp++) {
                uint32_t vh4[4], vl4[4];
                ldsm4(vh4, aVth + nfp * (16 * AROW) + kf * 32 + rowoffB);
                ldsm4(vl4, aVtl + nfp * (16 * AROW) + kf * 32 + rowoffB);
                mma_bf16(O[2 * nfp],     ph[kf], &vh4[0]);
                mma_bf16(O[2 * nfp],     ph[kf], &vl4[0]);
                mma_bf16(O[2 * nfp],     pl[kf], &vh4[0]);
                mma_bf16(O[2 * nfp + 1], ph[kf], &vh4[2]);
                mma_bf16(O[2 * nfp + 1], ph[kf], &vl4[2]);
                mma_bf16(O[2 * nfp + 1], pl[kf], &vh4[2]);
            }
        }

        __syncthreads();
        if (kt + 2 < 32) fill(kt & 1, (kt + 2) * 64);
    }

    // ---- epilogue ----
    float inv0 = 1.0f / l0r, inv1 = 1.0f / l1r;
    int b = bh >> 3, h = bh & 7;
#pragma unroll
    for (int nf = 0; nf < 8; nf++) {
        int d = nf * 8 + qt * 2;
        float2 o0 = make_float2(O[nf][0] * inv0, O[nf][1] * inv0);
        float2 o1 = make_float2(O[nf][2] * inv1, O[nf][3] * inv1);
        *(float2*)&out[((size_t)(b * SS) + r0) * HD + h * 64 + d]       = o0;
        *(float2*)&out[((size_t)(b * SS) + r0 + 8) * HD + h * 64 + d]   = o1;
    }
}

// ---------------------------------------------------------------------------
extern "C" void kernel_launch(void* const* d_in, const int* in_sizes, int n_in,
                              void* d_out, int out_size)
{
    const float* x  = (const float*)d_in[0];
    const float* Wq = (const float*)d_in[1];
    const float* bq = (const float*)d_in[2];
    const float* Wk = (const float*)d_in[3];
    const float* bk = (const float*)d_in[4];
    const float* Wv = (const float*)d_in[5];
    const float* bv = (const float*)d_in[6];
    const float* ah = (const float*)d_in[7];
    const float* vh = (const float*)d_in[8];
    float* out = (float*)d_out;

    zhat_kernel<<<SS / 256, 256>>>(ah, vh);
    split_kernel<<<(NX4 + NW4) / 256, 256>>>(x, Wq, Wk, Wv);

    cudaFuncSetAttribute(proj_mma,
                         cudaFuncAttributeMaxDynamicSharedMemorySize, PROJ_SMEM);
    proj_mma<<<dim3(12, 64), 256, PROJ_SMEM>>>(bq, bk, bv);

    cudaFuncSetAttribute(attn_mma,
                         cudaFuncAttributeMaxDynamicSharedMemorySize, ATTN_SMEM);
    attn_mma<<<dim3(SS / 128, BB * HH), 256, ATTN_SMEM>>>(out);
}

// round 7
// speedup vs baseline: 2.9354x; 1.0440x over previous
#include <cuda_runtime.h>
#include <cuda_bf16.h>
#include <math.h>
#include <stdint.h>

#define BB 4
#define SS 2048
#define FF 512
#define HH 8
#define DD 64
#define HD 512
#define MT (BB*SS)   // 8192

// ---------------------------------------------------------------------------
// Scratch (static device globals = sanctioned scratch path)
// ---------------------------------------------------------------------------
__device__ __nv_bfloat16 g_Xh[MT*FF];
__device__ __nv_bfloat16 g_Xl[MT*FF];
__device__ __nv_bfloat16 g_Wh[3*HD*FF];
__device__ __nv_bfloat16 g_Wl[3*HD*FF];
__device__ __nv_bfloat16 g_Qh[BB*HH*SS*DD];
__device__ __nv_bfloat16 g_Ql[BB*HH*SS*DD];
__device__ __nv_bfloat16 g_Kh[BB*HH*SS*DD];
__device__ __nv_bfloat16 g_Kl[BB*HH*SS*DD];
__device__ __nv_bfloat16 g_Vth[BB*HH*DD*SS];   // transposed: [b,h,d,s]
__device__ __nv_bfloat16 g_Vtl[BB*HH*DD*SS];   // transposed: [b,h,d,s]
__device__ float g_zt[SS];                      // zt * log2(e) (log2-domain logits)

// ---------------------------------------------------------------------------
// Helpers
// ---------------------------------------------------------------------------
__device__ __forceinline__ uint32_t smem_u32(const void* p) {
    uint32_t a;
    asm("{ .reg .u64 t; cvta.to.shared.u64 t, %1; cvt.u32.u64 %0, t; }"
        : "=r"(a) : "l"(p));
    return a;
}

#define CP_ASYNC16(dst, src) \
    asm volatile("cp.async.cg.shared.global [%0], [%1], 16;" \
        :: "r"(dst), "l"(src) : "memory")
#define CP_COMMIT() asm volatile("cp.async.commit_group;" ::: "memory")
#define CP_WAIT1()  asm volatile("cp.async.wait_group 1;" ::: "memory")

__device__ __forceinline__ void mma_bf16(float* d, const uint32_t* a, const uint32_t* b) {
    asm volatile(
        "mma.sync.aligned.m16n8k16.row.col.f32.bf16.bf16.f32 "
        "{%0,%1,%2,%3}, {%4,%5,%6,%7}, {%8,%9}, {%0,%1,%2,%3};"
        : "+f"(d[0]), "+f"(d[1]), "+f"(d[2]), "+f"(d[3])
        : "r"(a[0]), "r"(a[1]), "r"(a[2]), "r"(a[3]), "r"(b[0]), "r"(b[1]));
}

__device__ __forceinline__ void ldsm4(uint32_t* r, uint32_t addr) {
    asm volatile("ldmatrix.sync.aligned.m8n8.x4.shared.b16 {%0,%1,%2,%3}, [%4];"
        : "=r"(r[0]), "=r"(r[1]), "=r"(r[2]), "=r"(r[3]) : "r"(addr));
}

__device__ __forceinline__ uint32_t pk2(__nv_bfloat16 a, __nv_bfloat16 b) {
    return (uint32_t)__bfloat16_as_ushort(a) | ((uint32_t)__bfloat16_as_ushort(b) << 16);
}

__device__ __forceinline__ float ex2f(float x) {
    float y;
    asm("ex2.approx.f32 %0, %1;" : "=f"(y) : "f"(x));
    return y;
}

// ---------------------------------------------------------------------------
// z_hat table (log2-domain: includes 1/sqrt(D) and log2(e))
// ---------------------------------------------------------------------------
__global__ void zhat_kernel(const float* __restrict__ ah, const float* __restrict__ vh)
{
    int i = blockIdx.x * blockDim.x + threadIdx.x;
    if (i < SS) {
        float a = ah[0], v = vh[0];
        float z = 1.0f + expf(v) / (1.0f + expf(v - a * (float)i));
        g_zt[i] = z * 0.125f * 1.4426950408889634f;
    }
}

// ---------------------------------------------------------------------------
// Split X and W (fp32 -> bf16 hi + bf16 lo)
// ---------------------------------------------------------------------------
#define NX4 (MT*FF/4)
#define NW4 (3*HD*FF/4)
#define NW4_1 (HD*FF/4)

__global__ __launch_bounds__(256) void split_kernel(
    const float* __restrict__ X, const float* __restrict__ Wq,
    const float* __restrict__ Wk, const float* __restrict__ Wv)
{
    int i = blockIdx.x * 256 + threadIdx.x;
    const float* src;
    __nv_bfloat16 *dh, *dl;
    int off;
    if (i < NX4) {
        src = X; off = i; dh = g_Xh; dl = g_Xl;
    } else {
        int j = i - NX4;
        if (j < NW4_1)            { src = Wq; off = j; }
        else if (j < 2 * NW4_1)   { src = Wk; off = j - NW4_1; }
        else                      { src = Wv; off = j - 2 * NW4_1; }
        dh = g_Wh + (size_t)(j / NW4_1) * HD * FF;
        dl = g_Wl + (size_t)(j / NW4_1) * HD * FF;
    }
    float4 v = ((const float4*)src)[off];
    float vv[4] = {v.x, v.y, v.z, v.w};
    __nv_bfloat16 h[4], l[4];
#pragma unroll
    for (int k = 0; k < 4; k++) {
        h[k] = __float2bfloat16(vv[k]);
        l[k] = __float2bfloat16(vv[k] - __bfloat162float(h[k]));
    }
    size_t o4 = (size_t)off * 4;
    *(__nv_bfloat162*)&dh[o4]     = *(__nv_bfloat162*)&h[0];
    *(__nv_bfloat162*)&dh[o4 + 2] = *(__nv_bfloat162*)&h[2];
    *(__nv_bfloat162*)&dl[o4]     = *(__nv_bfloat162*)&l[0];
    *(__nv_bfloat162*)&dl[o4 + 2] = *(__nv_bfloat162*)&l[2];
}

// ---------------------------------------------------------------------------
// Fused QKV projection via mma.sync + ldmatrix, bf16x3 split. (unchanged)
// ---------------------------------------------------------------------------
#define PROW 144
#define PARR 18432
#define PSTG (4*PARR)
#define PROJ_SMEM (2*PSTG)

__global__ __launch_bounds__(256) void proj_mma(
    const float* __restrict__ bq, const float* __restrict__ bk,
    const float* __restrict__ bv)
{
    extern __shared__ char sm[];
    const uint32_t sbase = smem_u32(sm);
    const int tid = threadIdx.x;
    const int w = tid >> 5, lane = tid & 31;
    const int gr = lane >> 2, qt = lane & 3;
    const int nb = blockIdx.x;
    const int m0 = blockIdx.y * 128;

    const uint32_t rowoffB = (uint32_t)(((lane & 7) + ((lane >> 4) << 3)) * PROW
                                        + ((lane >> 3) & 1) * 16);
    const uint32_t rowoffA = (uint32_t)(((lane & 7) + (((lane >> 3) & 1) << 3)) * PROW
                                        + (lane >> 4) * 16);

    float acc[16][4];
#pragma unroll
    for (int i = 0; i < 16; i++)
#pragma unroll
        for (int j = 0; j < 4; j++) acc[i][j] = 0.f;

    auto fill = [&](int stg, int k0) {
        char* dstb = sm + stg * PSTG;
#pragma unroll
        for (int ii = 0; ii < 16; ii++) {
            int idx = ii * 256 + tid;
            int arr = idx >> 10;
            int r = (idx >> 3) & 127;
            int c = idx & 7;
            const __nv_bfloat16* src;
            if (arr == 0)      src = g_Xh + (size_t)(m0 + r) * FF + k0 + c * 8;
            else if (arr == 1) src = g_Xl + (size_t)(m0 + r) * FF + k0 + c * 8;
            else if (arr == 2) src = g_Wh + (size_t)(nb * 128 + r) * FF + k0 + c * 8;
            else               src = g_Wl + (size_t)(nb * 128 + r) * FF + k0 + c * 8;
            uint32_t d = smem_u32(dstb + arr * PARR + r * PROW + c * 16);
            CP_ASYNC16(d, src);
        }
        CP_COMMIT();
    };

    fill(0, 0);
    fill(1, 64);

    const uint32_t w16off = (uint32_t)(w * 16 * PROW);
#pragma unroll 1
    for (int ks = 0; ks < 8; ks++) {
        CP_WAIT1();
        __syncthreads();
        const uint32_t B   = sbase + (ks & 1) * PSTG;
        const uint32_t aXh = B;
        const uint32_t aXl = B + PARR;
        const uint32_t aWh = B + 2 * PARR;
        const uint32_t aWl = B + 3 * PARR;
#pragma unroll
        for (int kf = 0; kf < 4; kf++) {
            uint32_t xh[4], xl[4];
            ldsm4(xh, aXh + w16off + kf * 32 + rowoffA);
            ldsm4(xl, aXl + w16off + kf * 32 + rowoffA);
#pragma unroll
            for (int nfp = 0; nfp < 8; nfp++) {
                uint32_t wh4[4], wl4[4];
                ldsm4(wh4, aWh + nfp * (16 * PROW) + kf * 32 + rowoffB);
                ldsm4(wl4, aWl + nfp * (16 * PROW) + kf * 32 + rowoffB);
                mma_bf16(acc[2 * nfp],     xh, &wh4[0]);
                mma_bf16(acc[2 * nfp],     xh, &wl4[0]);
                mma_bf16(acc[2 * nfp],     xl, &wh4[0]);
                mma_bf16(acc[2 * nfp + 1], xh, &wh4[2]);
                mma_bf16(acc[2 * nfp + 1], xh, &wl4[2]);
                mma_bf16(acc[2 * nfp + 1], xl, &wh4[2]);
            }
        }
        __syncthreads();
        if (ks + 2 < 8) fill(ks & 1, (ks + 2) * 64);
    }

    const int r0 = m0 + w * 16 + gr;
#pragma unroll
    for (int nf = 0; nf < 16; nf++) {
        int ng = nb * 128 + nf * 8 + qt * 2;
        int sel = ng >> 9;
        int within = ng & 511;
        const float* bias = (sel == 0) ? bq : (sel == 1) ? bk : bv;
        float b0 = bias[within], b1 = bias[within + 1];
        int h = within >> 6, d = within & 63;
#pragma unroll
        for (int half = 0; half < 2; half++) {
            int m = r0 + half * 8;
            int bb = m >> 11, s = m & 2047;
            float y0 = acc[nf][half * 2 + 0] + b0;
            float y1 = acc[nf][half * 2 + 1] + b1;
            __nv_bfloat16 h0 = __float2bfloat16(y0);
            __nv_bfloat16 h1 = __float2bfloat16(y1);
            __nv_bfloat16 l0 = __float2bfloat16(y0 - __bfloat162float(h0));
            __nv_bfloat16 l1 = __float2bfloat16(y1 - __bfloat162float(h1));
            if (sel < 2) {
                __nv_bfloat16* dh = (sel == 0) ? g_Qh : g_Kh;
                __nv_bfloat16* dl = (sel == 0) ? g_Ql : g_Kl;
                size_t a = (((size_t)(bb * HH + h)) * SS + s) * DD + d;
                *(uint32_t*)&dh[a] = pk2(h0, h1);
                *(uint32_t*)&dl[a] = pk2(l0, l1);
            } else {
                size_t a0 = (((size_t)(bb * HH + h)) * DD + d) * SS + s;
                size_t a1 = a0 + SS;
                g_Vth[a0] = h0; g_Vth[a1] = h1;
                g_Vtl[a0] = l0; g_Vtl[a1] = l1;
            }
        }
    }
}

// ---------------------------------------------------------------------------
// Flash attention: 128-thread CTAs (4 warps, 64 q-rows), 32-key tiles,
// 4 CTAs/SM for phase-decorrelated overlap. bf16x3 everywhere.
// ---------------------------------------------------------------------------
#define KROW 144               // 32 key-rows x (128B data + 16 pad)
#define VROW 80                // 64 d-rows  x (64B data + 16 pad)
#define KARR (32*KROW)         // 4608
#define VARR (64*VROW)         // 5120
#define ASTG (2*KARR + 2*VARR) // 19456
#define AZT  (2*ASTG)          // 38912
#define ATTN_SMEM (AZT + SS*4) // 47104

__global__ __launch_bounds__(128, 4) void attn_mma(float* __restrict__ out)
{
    extern __shared__ char sm[];
    const uint32_t sbase = smem_u32(sm);
    float* zts = (float*)(sm + AZT);
    const int tid = threadIdx.x;
    const int w = tid >> 5, lane = tid & 31;
    const int gr = lane >> 2, qt = lane & 3;
    const int bh = blockIdx.y;
    const int q0 = blockIdx.x * 64;

    const uint32_t rowK = (uint32_t)(((lane & 7) + ((lane >> 4) << 3)) * KROW
                                     + ((lane >> 3) & 1) * 16);
    const uint32_t rowV = (uint32_t)(((lane & 7) + ((lane >> 4) << 3)) * VROW
                                     + ((lane >> 3) & 1) * 16);

    for (int i = tid; i < SS; i += 128) zts[i] = g_zt[i];

    // Q fragments straight from gmem (once)
    const int r0 = q0 + w * 16 + gr;
    const __nv_bfloat16* Qh = g_Qh + (size_t)bh * SS * DD;
    const __nv_bfloat16* Ql = g_Ql + (size_t)bh * SS * DD;
    uint32_t qah[4][4], qal[4][4];
#pragma unroll
    for (int kf = 0; kf < 4; kf++) {
        int col = kf * 16 + qt * 2;
        qah[kf][0] = *(const uint32_t*)(Qh + (size_t)r0 * 64 + col);
        qah[kf][1] = *(const uint32_t*)(Qh + (size_t)(r0 + 8) * 64 + col);
        qah[kf][2] = *(const uint32_t*)(Qh + (size_t)r0 * 64 + col + 8);
        qah[kf][3] = *(const uint32_t*)(Qh + (size_t)(r0 + 8) * 64 + col + 8);
        qal[kf][0] = *(const uint32_t*)(Ql + (size_t)r0 * 64 + col);
        qal[kf][1] = *(const uint32_t*)(Ql + (size_t)(r0 + 8) * 64 + col);
        qal[kf][2] = *(const uint32_t*)(Ql + (size_t)r0 * 64 + col + 8);
        qal[kf][3] = *(const uint32_t*)(Ql + (size_t)(r0 + 8) * 64 + col + 8);
    }

    auto fill = [&](int stg, int k0) {
        char* dstb = sm + stg * ASTG;
#pragma unroll
        for (int ii = 0; ii < 8; ii++) {
            int idx = ii * 128 + tid;       // 0..1023
            int arr = idx >> 8;             // 0..3
            const __nv_bfloat16* src;
            uint32_t d;
            if (arr < 2) {
                int r = (idx >> 3) & 31, c = idx & 7;
                src = ((arr == 0) ? g_Kh : g_Kl) + ((size_t)bh * SS + k0 + r) * 64 + c * 8;
                d = smem_u32(dstb + arr * KARR + r * KROW + c * 16);
            } else {
                int j = idx & 255;
                int r = j >> 2, c = j & 3;
                src = ((arr == 2) ? g_Vth : g_Vtl) + ((size_t)bh * DD + r) * SS + k0 + c * 8;
                d = smem_u32(dstb + 2 * KARR + (arr - 2) * VARR + r * VROW + c * 16);
            }
            CP_ASYNC16(d, src);
        }
        CP_COMMIT();
    };

    fill(0, 0);
    fill(1, 32);

    float O[8][4];
#pragma unroll
    for (int i = 0; i < 8; i++)
#pragma unroll
        for (int j = 0; j < 4; j++) O[i][j] = 0.f;
    float m0r = -1e30f, m1r = -1e30f, l0r = 0.f, l1r = 0.f;

#pragma unroll 1
    for (int kt = 0; kt < 64; kt++) {
        CP_WAIT1();
        __syncthreads();
        const uint32_t B    = sbase + (kt & 1) * ASTG;
        const uint32_t aKh  = B;
        const uint32_t aKl  = B + KARR;
        const uint32_t aVth = B + 2 * KARR;
        const uint32_t aVtl = B + 2 * KARR + VARR;
        const int k0 = kt * 32;

        // ---- S = Q K^T (bf16x3) ----
        float S[4][4];
#pragma unroll
        for (int i = 0; i < 4; i++)
#pragma unroll
            for (int j = 0; j < 4; j++) S[i][j] = 0.f;

#pragma unroll
        for (int kf = 0; kf < 4; kf++) {
#pragma unroll
            for (int nfp = 0; nfp < 2; nfp++) {
                uint32_t rh[4], rl[4];
                ldsm4(rh, aKh + nfp * (16 * KROW) + kf * 32 + rowK);
                ldsm4(rl, aKl + nfp * (16 * KROW) + kf * 32 + rowK);
                mma_bf16(S[2 * nfp],     qah[kf], &rh[0]);
                mma_bf16(S[2 * nfp],     qah[kf], &rl[0]);
                mma_bf16(S[2 * nfp],     qal[kf], &rh[0]);
                mma_bf16(S[2 * nfp + 1], qah[kf], &rh[2]);
                mma_bf16(S[2 * nfp + 1], qah[kf], &rl[2]);
                mma_bf16(S[2 * nfp + 1], qal[kf], &rh[2]);
            }
        }

        // ---- bias + online softmax (log2 domain) ----
        float mt0 = -1e30f, mt1 = -1e30f;
#pragma unroll
        for (int nf = 0; nf < 4; nf++) {
            int c0 = k0 + nf * 8 + qt * 2;
            S[nf][0] *= zts[abs(r0 - c0)];
            S[nf][1] *= zts[abs(r0 - c0 - 1)];
            S[nf][2] *= zts[abs(r0 + 8 - c0)];
            S[nf][3] *= zts[abs(r0 + 8 - c0 - 1)];
            mt0 = fmaxf(mt0, fmaxf(S[nf][0], S[nf][1]));
            mt1 = fmaxf(mt1, fmaxf(S[nf][2], S[nf][3]));
        }
        mt0 = fmaxf(mt0, __shfl_xor_sync(0xffffffffu, mt0, 1));
        mt0 = fmaxf(mt0, __shfl_xor_sync(0xffffffffu, mt0, 2));
        mt1 = fmaxf(mt1, __shfl_xor_sync(0xffffffffu, mt1, 1));
        mt1 = fmaxf(mt1, __shfl_xor_sync(0xffffffffu, mt1, 2));
        float mn0 = fmaxf(m0r, mt0), mn1 = fmaxf(m1r, mt1);
        float a0 = ex2f(m0r - mn0), a1 = ex2f(m1r - mn1);
        m0r = mn0; m1r = mn1;

        float s0 = 0.f, s1 = 0.f;
        uint32_t ph[2][4], pl[2][4];
#pragma unroll
        for (int nf = 0; nf < 4; nf++) {
            float e0 = ex2f(S[nf][0] - mn0);
            float e1 = ex2f(S[nf][1] - mn0);
            float e2 = ex2f(S[nf][2] - mn1);
            float e3 = ex2f(S[nf][3] - mn1);
            s0 += e0 + e1; s1 += e2 + e3;
            __nv_bfloat16 h0 = __float2bfloat16(e0);
            __nv_bfloat16 h1 = __float2bfloat16(e1);
            __nv_bfloat16 h2 = __float2bfloat16(e2);
            __nv_bfloat16 h3 = __float2bfloat16(e3);
            __nv_bfloat16 g0 = __float2bfloat16(e0 - __bfloat162float(h0));
            __nv_bfloat16 g1 = __float2bfloat16(e1 - __bfloat162float(h1));
            __nv_bfloat16 g2 = __float2bfloat16(e2 - __bfloat162float(h2));
            __nv_bfloat16 g3 = __float2bfloat16(e3 - __bfloat162float(h3));
            int kf = nf >> 1;
            if ((nf & 1) == 0) {
                ph[kf][0] = pk2(h0, h1); ph[kf][1] = pk2(h2, h3);
                pl[kf][0] = pk2(g0, g1); pl[kf][1] = pk2(g2, g3);
            } else {
                ph[kf][2] = pk2(h0, h1); ph[kf][3] = pk2(h2, h3);
                pl[kf][2] = pk2(g0, g1); pl[kf][3] = pk2(g2, g3);
            }
        }
        s0 += __shfl_xor_sync(0xffffffffu, s0, 1);
        s0 += __shfl_xor_sync(0xffffffffu, s0, 2);
        s1 += __shfl_xor_sync(0xffffffffu, s1, 1);
        s1 += __shfl_xor_sync(0xffffffffu, s1, 2);
        l0r = l0r * a0 + s0;
        l1r = l1r * a1 + s1;
#pragma unroll
        for (int nf = 0; nf < 8; nf++) {
            O[nf][0] *= a0; O[nf][1] *= a0;
            O[nf][2] *= a1; O[nf][3] *= a1;
        }

        // ---- O += P V (bf16x3) ----
#pragma unroll
        for (int kf = 0; kf < 2; kf++) {
#pragma unroll
            for (int nfp = 0; nfp < 4; nfp++) {
                uint32_t vh4[4], vl4[4];
                ldsm4(vh4, aVth + nfp * (16 * VROW) + kf * 32 + rowV);
                ldsm4(vl4, aVtl + nfp * (16 * VROW) + kf * 32 + rowV);
                mma_bf16(O[2 * nfp],     ph[kf], &vh4[0]);
                mma_bf16(O[2 * nfp],     ph[kf], &vl4[0]);
                mma_bf16(O[2 * nfp],     pl[kf], &vh4[0]);
                mma_bf16(O[2 * nfp + 1], ph[kf], &vh4[2]);
                mma_bf16(O[2 * nfp + 1], ph[kf], &vl4[2]);
                mma_bf16(O[2 * nfp + 1], pl[kf], &vh4[2]);
            }
        }

        __syncthreads();
        if (kt + 2 < 64) fill(kt & 1, (kt + 2) * 32);
    }

    // ---- epilogue ----
    float inv0 = 1.0f / l0r, inv1 = 1.0f / l1r;
    int b = bh >> 3, h = bh & 7;
#pragma unroll
    for (int nf = 0; nf < 8; nf++) {
        int d = nf * 8 + qt * 2;
        float2 o0 = make_float2(O[nf][0] * inv0, O[nf][1] * inv0);
        float2 o1 = make_float2(O[nf][2] * inv1, O[nf][3] * inv1);
        *(float2*)&out[((size_t)(b * SS) + r0) * HD + h * 64 + d]       = o0;
        *(float2*)&out[((size_t)(b * SS) + r0 + 8) * HD + h * 64 + d]   = o1;
    }
}

// ---------------------------------------------------------------------------
extern "C" void kernel_launch(void* const* d_in, const int* in_sizes, int n_in,
                              void* d_out, int out_size)
{
    const float* x  = (const float*)d_in[0];
    const float* Wq = (const float*)d_in[1];
    const float* bq = (const float*)d_in[2];
    const float* Wk = (const float*)d_in[3];
    const float* bk = (const float*)d_in[4];
    const float* Wv = (const float*)d_in[5];
    const float* bv = (const float*)d_in[6];
    const float* ah = (const float*)d_in[7];
    const float* vh = (const float*)d_in[8];
    float* out = (float*)d_out;

    zhat_kernel<<<SS / 256, 256>>>(ah, vh);
    split_kernel<<<(NX4 + NW4) / 256, 256>>>(x, Wq, Wk, Wv);

    cudaFuncSetAttribute(proj_mma,
                         cudaFuncAttributeMaxDynamicSharedMemorySize, PROJ_SMEM);
    proj_mma<<<dim3(12, 64), 256, PROJ_SMEM>>>(bq, bk, bv);

    cudaFuncSetAttribute(attn_mma,
                         cudaFuncAttributeMaxDynamicSharedMemorySize, ATTN_SMEM);
    attn_mma<<<dim3(SS / 64, BB * HH), 128, ATTN_SMEM>>>(out);
}